// round 1
// baseline (speedup 1.0000x reference)
#include <cuda_runtime.h>
#include <cstdint>

#define B_ 64
#define N_ 512
#define M_ 1024
#define D_ 128

typedef unsigned long long ull;

// Scratch (allocation-free: device globals)
__device__ float g_Uc[(size_t)B_ * N_ * D_];     // 16.8 MB
__device__ float g_Vp[(size_t)B_ * M_ * D_];     // 33.6 MB
__device__ float g_part[(size_t)B_ * 32 * D_];   // per-(b, n-tile) partial sums

// ---------- packed f32x2 helpers ----------
__device__ __forceinline__ ull ffma2(ull a, ull b, ull c) {
    ull d;
    asm("fma.rn.f32x2 %0, %1, %2, %3;" : "=l"(d) : "l"(a), "l"(b), "l"(c));
    return d;
}
__device__ __forceinline__ ull pack2(float x, float y) {
    ull r; asm("mov.b64 %0, {%1, %2};" : "=l"(r) : "f"(x), "f"(y)); return r;
}
__device__ __forceinline__ float2 unpack2(ull v) {
    float2 f; asm("mov.b64 {%0, %1}, %2;" : "=f"(f.x), "=f"(f.y) : "l"(v)); return f;
}

// ============================================================================
// Projection: out[r][c] = relu( sum_d X[r][d] * W[c][d] + bias[c] )
// Block: 64 rows x 128 cols. 256 threads, thread tile 4r x 8c, FFMA2 over d.
// W in SMEM with XOR-quad swizzle (rows of W are d-contiguous -> LDS.128).
// ============================================================================
__global__ __launch_bounds__(256)
void proj_kernel(const float* __restrict__ X, const float* __restrict__ W,
                 const float* __restrict__ bias, float* __restrict__ out) {
    extern __shared__ float sm[];
    float* Ws = sm;            // 128*128 swizzled
    float* Xs = sm + 16384;    // 64 rows, stride 132 (pad)

    const int tid = threadIdx.x;
    const size_t row0 = (size_t)blockIdx.x * 64;

    // Load W (16384 floats) swizzled: Ws[c*128 + (d ^ (((c>>3)&7)<<2))]
    #pragma unroll
    for (int it = 0; it < 16; it++) {
        int i = it * 1024 + tid * 4;
        int c = i >> 7, d = i & 127;
        float4 v = *(const float4*)&W[i];
        int dsw = d ^ (((c >> 3) & 7) << 2);
        *(float4*)&Ws[c * 128 + dsw] = v;
    }
    // Load X tile (64x128), padded stride 132
    #pragma unroll
    for (int it = 0; it < 8; it++) {
        int i = it * 1024 + tid * 4;
        int r = i >> 7, d = i & 127;
        *(float4*)&Xs[r * 132 + d] = *(const float4*)&X[row0 * D_ + i];
    }
    __syncthreads();

    const int cg = tid & 15, rg = tid >> 4;
    const int r0 = rg * 4, c0 = cg * 8;
    const int swz = (cg & 7) << 2;   // (c0>>3)&7 << 2, same for c0..c0+7

    ull acc[4][8];
    #pragma unroll
    for (int i = 0; i < 4; i++)
        #pragma unroll
        for (int j = 0; j < 8; j++) acc[i][j] = 0ULL;

    #pragma unroll 2
    for (int d = 0; d < 128; d += 4) {
        ulonglong2 x[4];
        #pragma unroll
        for (int i = 0; i < 4; i++)
            x[i] = *(const ulonglong2*)&Xs[(r0 + i) * 132 + d];
        const int dsw = d ^ swz;
        #pragma unroll
        for (int j = 0; j < 8; j++) {
            ulonglong2 wv = *(const ulonglong2*)&Ws[(c0 + j) * 128 + dsw];
            #pragma unroll
            for (int i = 0; i < 4; i++) {
                acc[i][j] = ffma2(x[i].x, wv.x, acc[i][j]);
                acc[i][j] = ffma2(x[i].y, wv.y, acc[i][j]);
            }
        }
    }

    // Epilogue: horizontal add + bias + relu, vectorized stores
    #pragma unroll
    for (int i = 0; i < 4; i++) {
        float o[8];
        #pragma unroll
        for (int j = 0; j < 8; j++) {
            float2 p = unpack2(acc[i][j]);
            float v = p.x + p.y + bias[c0 + j];
            o[j] = fmaxf(v, 0.0f);
        }
        float* op = &out[(row0 + r0 + i) * D_ + c0];
        *(float4*)&op[0] = make_float4(o[0], o[1], o[2], o[3]);
        *(float4*)&op[4] = make_float4(o[4], o[5], o[6], o[7]);
    }
}

// ============================================================================
// Fused attention: per block = (batch b, 16-row n-tile).
//   Phase 1: scores S[16][1024] = Uc_tile @ Vp^T   (Vp streamed in 128-row
//            swizzled SMEM chunks)
//   Phase 2: in-SMEM softmax (max, exp, sum) per row
//   Phase 3: context accumulation ctx = W @ Vp  (second stream of Vp chunks)
//   Epilogue: partial[d] = sum_n (Uc + ctx/l), written to g_part
// ============================================================================
__global__ __launch_bounds__(256)
void attn_kernel(const float* __restrict__ Uc, const float* __restrict__ Vp,
                 float* __restrict__ part) {
    extern __shared__ float sm[];
    float* S     = sm;             // 16*1024
    float* Vps   = sm + 16384;     // 128*128 swizzled chunk
    float* Ucs   = sm + 32768;     // 16*128
    float* ppart = sm + 34816;     // 128
    float* invl  = sm + 34944;     // 16

    const int tid = threadIdx.x;
    const int b  = blockIdx.x >> 5;
    const int nt = blockIdx.x & 31;
    const int n0 = nt * 16;

    const float* ucg = Uc + ((size_t)b * N_ + n0) * D_;
    const float* vpg = Vp + (size_t)b * M_ * D_;

    // Load Uc tile (2048 floats)
    #pragma unroll
    for (int it = 0; it < 2; it++) {
        int i = it * 1024 + tid * 4;
        *(float4*)&Ucs[i] = *(const float4*)&ucg[i];
    }
    if (tid < 128) ppart[tid] = 0.0f;

    // ---------------- Phase 1: scores ----------------
    const int mg = tid & 31, ng = tid >> 5;        // warp = one ng (2 n-rows)
    const int m0 = mg * 4;
    const int swzS = ((m0 >> 2) & 7) << 2;

    for (int ch = 0; ch < 8; ch++) {
        __syncthreads();
        // Stage Vp chunk (128 rows x 128), XOR-quad swizzled
        #pragma unroll
        for (int it = 0; it < 16; it++) {
            int i = it * 1024 + tid * 4;
            int m = i >> 7, d = i & 127;
            float4 v = *(const float4*)&vpg[(size_t)ch * 16384 + i];
            *(float4*)&Vps[m * 128 + (d ^ (((m >> 2) & 7) << 2))] = v;
        }
        __syncthreads();

        ull acc[2][4];
        #pragma unroll
        for (int t = 0; t < 2; t++)
            #pragma unroll
            for (int j = 0; j < 4; j++) acc[t][j] = 0ULL;

        const float* uc0 = &Ucs[(2 * ng) * 128];
        const float* uc1 = &Ucs[(2 * ng + 1) * 128];
        #pragma unroll 4
        for (int d = 0; d < 128; d += 4) {
            ulonglong2 u0 = *(const ulonglong2*)&uc0[d];
            ulonglong2 u1 = *(const ulonglong2*)&uc1[d];
            const int dsw = d ^ swzS;
            #pragma unroll
            for (int j = 0; j < 4; j++) {
                ulonglong2 vv = *(const ulonglong2*)&Vps[(m0 + j) * 128 + dsw];
                acc[0][j] = ffma2(u0.x, vv.x, acc[0][j]);
                acc[0][j] = ffma2(u0.y, vv.y, acc[0][j]);
                acc[1][j] = ffma2(u1.x, vv.x, acc[1][j]);
                acc[1][j] = ffma2(u1.y, vv.y, acc[1][j]);
            }
        }
        #pragma unroll
        for (int t = 0; t < 2; t++) {
            float2 p0 = unpack2(acc[t][0]);
            float2 p1 = unpack2(acc[t][1]);
            float2 p2 = unpack2(acc[t][2]);
            float2 p3 = unpack2(acc[t][3]);
            *(float4*)&S[(2 * ng + t) * 1024 + ch * 128 + m0] =
                make_float4(p0.x + p0.y, p1.x + p1.y, p2.x + p2.y, p3.x + p3.y);
        }
    }
    __syncthreads();

    // ---------------- Phase 2: softmax (exp kept unnormalized; 1/sum saved) ----
    {
        const int w = tid >> 5, lane = tid & 31;
        #pragma unroll
        for (int t = 0; t < 2; t++) {
            int row = 2 * w + t;
            float* sr = &S[row * 1024];
            float mx = -1e30f;
            #pragma unroll
            for (int k = 0; k < 32; k++) mx = fmaxf(mx, sr[k * 32 + lane]);
            #pragma unroll
            for (int off = 16; off; off >>= 1)
                mx = fmaxf(mx, __shfl_xor_sync(0xffffffffu, mx, off));
            float sum = 0.0f;
            #pragma unroll
            for (int k = 0; k < 32; k++) {
                float e = __expf(sr[k * 32 + lane] - mx);
                sr[k * 32 + lane] = e;
                sum += e;
            }
            #pragma unroll
            for (int off = 16; off; off >>= 1)
                sum += __shfl_xor_sync(0xffffffffu, sum, off);
            if (lane == 0) invl[row] = 1.0f / sum;
        }
    }

    // ---------------- Phase 3: context ----------------
    const int dq = tid & 31, ng2 = tid >> 5;       // warp = one ng2 (2 n-rows)
    const int d0 = dq * 4;
    ull cacc[2][2];
    cacc[0][0] = cacc[0][1] = cacc[1][0] = cacc[1][1] = 0ULL;

    for (int ch = 0; ch < 8; ch++) {
        __syncthreads();
        #pragma unroll
        for (int it = 0; it < 16; it++) {
            int i = it * 1024 + tid * 4;
            int m = i >> 7, d = i & 127;
            float4 v = *(const float4*)&vpg[(size_t)ch * 16384 + i];
            *(float4*)&Vps[m * 128 + (d ^ (((m >> 2) & 7) << 2))] = v;
        }
        __syncthreads();

        const float* s0 = &S[(2 * ng2) * 1024 + ch * 128];
        const float* s1 = s0 + 1024;
        #pragma unroll 4
        for (int mm = 0; mm < 128; mm++) {
            ulonglong2 vv =
                *(const ulonglong2*)&Vps[mm * 128 + (d0 ^ (((mm >> 2) & 7) << 2))];
            float w0f = s0[mm], w1f = s1[mm];
            ull w0 = pack2(w0f, w0f);
            ull w1 = pack2(w1f, w1f);
            cacc[0][0] = ffma2(w0, vv.x, cacc[0][0]);
            cacc[0][1] = ffma2(w0, vv.y, cacc[0][1]);
            cacc[1][0] = ffma2(w1, vv.x, cacc[1][0]);
            cacc[1][1] = ffma2(w1, vv.y, cacc[1][1]);
        }
    }

    // ---------------- Epilogue: sum over the 16 n-rows ----------------
    float j0 = 0.f, j1 = 0.f, j2 = 0.f, j3 = 0.f;
    #pragma unroll
    for (int t = 0; t < 2; t++) {
        const int n = 2 * ng2 + t;
        const float il = invl[n];
        float4 uc = *(const float4*)&Ucs[n * 128 + d0];
        float2 a = unpack2(cacc[t][0]);
        float2 c = unpack2(cacc[t][1]);
        j0 += uc.x + a.x * il;
        j1 += uc.y + a.y * il;
        j2 += uc.z + c.x * il;
        j3 += uc.w + c.y * il;
    }
    atomicAdd(&ppart[d0 + 0], j0);
    atomicAdd(&ppart[d0 + 1], j1);
    atomicAdd(&ppart[d0 + 2], j2);
    atomicAdd(&ppart[d0 + 3], j3);
    __syncthreads();
    if (tid < 128)
        part[(size_t)blockIdx.x * D_ + tid] = ppart[tid];
}

// ============================================================================
// Final reduce: out[b][d] = (q[d]/N) * sum_{nt} part[b][nt][d]
// ============================================================================
__global__ __launch_bounds__(256)
void reduce_kernel(const float* __restrict__ part, const float* __restrict__ q,
                   float* __restrict__ out) {
    int i = blockIdx.x * blockDim.x + threadIdx.x;
    int b = i >> 7, d = i & 127;
    float s = 0.0f;
    #pragma unroll
    for (int nt = 0; nt < 32; nt++)
        s += part[(size_t)((b << 5) + nt) * D_ + d];
    out[i] = s * q[d] * (1.0f / (float)N_);
}

// ============================================================================
extern "C" void kernel_launch(void* const* d_in, const int* in_sizes, int n_in,
                              void* d_out, int out_size) {
    const float* h_c = (const float*)d_in[0];
    const float* h_p = (const float*)d_in[1];
    const float* U_w = (const float*)d_in[2];
    const float* U_b = (const float*)d_in[3];
    const float* V_w = (const float*)d_in[4];
    const float* V_b = (const float*)d_in[5];
    const float* q   = (const float*)d_in[6];
    float* out = (float*)d_out;

    void *pUc, *pVp, *pPart;
    cudaGetSymbolAddress(&pUc, g_Uc);
    cudaGetSymbolAddress(&pVp, g_Vp);
    cudaGetSymbolAddress(&pPart, g_part);

    const int PROJ_SMEM = (16384 + 64 * 132) * 4;   // 99328 B
    const int ATTN_SMEM = 34960 * 4;                // 139840 B
    cudaFuncSetAttribute(proj_kernel,
                         cudaFuncAttributeMaxDynamicSharedMemorySize, PROJ_SMEM);
    cudaFuncSetAttribute(attn_kernel,
                         cudaFuncAttributeMaxDynamicSharedMemorySize, ATTN_SMEM);

    proj_kernel<<<(B_ * N_) / 64, 256, PROJ_SMEM>>>(h_c, U_w, U_b, (float*)pUc);
    proj_kernel<<<(B_ * M_) / 64, 256, PROJ_SMEM>>>(h_p, V_w, V_b, (float*)pVp);
    attn_kernel<<<B_ * 32, 256, ATTN_SMEM>>>((const float*)pUc,
                                             (const float*)pVp, (float*)pPart);
    reduce_kernel<<<(B_ * D_) / 256, 256>>>((const float*)pPart, q, out);
}

// round 2
// speedup vs baseline: 1.0034x; 1.0034x over previous
#include <cuda_runtime.h>
#include <cstdint>

#define B_ 64
#define N_ 512
#define M_ 1024
#define D_ 128

typedef unsigned long long ull;

// Scratch (allocation-free: device globals)
__device__ float g_Uc[(size_t)B_ * N_ * D_];     // 16.8 MB
__device__ float g_Vp[(size_t)B_ * M_ * D_];     // 33.6 MB
__device__ float g_part[(size_t)B_ * 32 * D_];   // per-(b, n-tile) partial sums

// ---------- packed f32x2 helpers ----------
__device__ __forceinline__ ull ffma2(ull a, ull b, ull c) {
    ull d;
    asm("fma.rn.f32x2 %0, %1, %2, %3;" : "=l"(d) : "l"(a), "l"(b), "l"(c));
    return d;
}
__device__ __forceinline__ ull pack2(float x, float y) {
    ull r; asm("mov.b64 %0, {%1, %2};" : "=l"(r) : "f"(x), "f"(y)); return r;
}
__device__ __forceinline__ float2 unpack2(ull v) {
    float2 f; asm("mov.b64 {%0, %1}, %2;" : "=f"(f.x), "=f"(f.y) : "l"(v)); return f;
}

// ============================================================================
// Projection: out[r][c] = relu( sum_d X[r][d] * W[c][d] + bias[c] )
// Block: 64 rows x 128 cols. 256 threads, thread tile 4r x 8c, FFMA2 over d.
// W in SMEM with XOR-quad swizzle (rows of W are d-contiguous -> LDS.128).
// ============================================================================
__global__ __launch_bounds__(256)
void proj_kernel(const float* __restrict__ X, const float* __restrict__ W,
                 const float* __restrict__ bias, float* __restrict__ out) {
    extern __shared__ float sm[];
    float* Ws = sm;            // 128*128 swizzled
    float* Xs = sm + 16384;    // 64 rows, stride 132 (pad)

    const int tid = threadIdx.x;
    const size_t row0 = (size_t)blockIdx.x * 64;

    // Load W (16384 floats) swizzled: Ws[c*128 + (d ^ (((c>>3)&7)<<2))]
    #pragma unroll
    for (int it = 0; it < 16; it++) {
        int i = it * 1024 + tid * 4;
        int c = i >> 7, d = i & 127;
        float4 v = *(const float4*)&W[i];
        int dsw = d ^ (((c >> 3) & 7) << 2);
        *(float4*)&Ws[c * 128 + dsw] = v;
    }
    // Load X tile (64x128), padded stride 132
    #pragma unroll
    for (int it = 0; it < 8; it++) {
        int i = it * 1024 + tid * 4;
        int r = i >> 7, d = i & 127;
        *(float4*)&Xs[r * 132 + d] = *(const float4*)&X[row0 * D_ + i];
    }
    __syncthreads();

    const int cg = tid & 15, rg = tid >> 4;
    const int r0 = rg * 4, c0 = cg * 8;
    const int swz = (cg & 7) << 2;   // (c0>>3)&7 << 2, same for c0..c0+7

    ull acc[4][8];
    #pragma unroll
    for (int i = 0; i < 4; i++)
        #pragma unroll
        for (int j = 0; j < 8; j++) acc[i][j] = 0ULL;

    #pragma unroll 2
    for (int d = 0; d < 128; d += 4) {
        ulonglong2 x[4];
        #pragma unroll
        for (int i = 0; i < 4; i++)
            x[i] = *(const ulonglong2*)&Xs[(r0 + i) * 132 + d];
        const int dsw = d ^ swz;
        #pragma unroll
        for (int j = 0; j < 8; j++) {
            ulonglong2 wv = *(const ulonglong2*)&Ws[(c0 + j) * 128 + dsw];
            #pragma unroll
            for (int i = 0; i < 4; i++) {
                acc[i][j] = ffma2(x[i].x, wv.x, acc[i][j]);
                acc[i][j] = ffma2(x[i].y, wv.y, acc[i][j]);
            }
        }
    }

    // Epilogue: horizontal add + bias + relu, vectorized stores
    #pragma unroll
    for (int i = 0; i < 4; i++) {
        float o[8];
        #pragma unroll
        for (int j = 0; j < 8; j++) {
            float2 p = unpack2(acc[i][j]);
            float v = p.x + p.y + bias[c0 + j];
            o[j] = fmaxf(v, 0.0f);
        }
        float* op = &out[(row0 + r0 + i) * D_ + c0];
        *(float4*)&op[0] = make_float4(o[0], o[1], o[2], o[3]);
        *(float4*)&op[4] = make_float4(o[4], o[5], o[6], o[7]);
    }
}

// ============================================================================
// Fused attention: per block = (batch b, 16-row n-tile).
//   Phase 1: scores S[16][1024] = Uc_tile @ Vp^T   (Vp streamed in 128-row
//            swizzled SMEM chunks)
//   Phase 2: in-SMEM softmax (max, exp, sum) per row
//   Phase 3: context accumulation ctx = W @ Vp  (second stream of Vp chunks)
//   Epilogue: partial[d] = sum_n (Uc + ctx/l), written to g_part
// ============================================================================
__global__ __launch_bounds__(256)
void attn_kernel(const float* __restrict__ Uc, const float* __restrict__ Vp,
                 float* __restrict__ part) {
    extern __shared__ float sm[];
    float* S     = sm;             // 16*1024
    float* Vps   = sm + 16384;     // 128*128 swizzled chunk
    float* Ucs   = sm + 32768;     // 16*128
    float* ppart = sm + 34816;     // 128
    float* invl  = sm + 34944;     // 16

    const int tid = threadIdx.x;
    const int b  = blockIdx.x >> 5;
    const int nt = blockIdx.x & 31;
    const int n0 = nt * 16;

    const float* ucg = Uc + ((size_t)b * N_ + n0) * D_;
    const float* vpg = Vp + (size_t)b * M_ * D_;

    // Load Uc tile (2048 floats)
    #pragma unroll
    for (int it = 0; it < 2; it++) {
        int i = it * 1024 + tid * 4;
        *(float4*)&Ucs[i] = *(const float4*)&ucg[i];
    }
    if (tid < 128) ppart[tid] = 0.0f;

    // ---------------- Phase 1: scores ----------------
    const int mg = tid & 31, ng = tid >> 5;        // warp = one ng (2 n-rows)
    const int m0 = mg * 4;
    const int swzS = ((m0 >> 2) & 7) << 2;

    for (int ch = 0; ch < 8; ch++) {
        __syncthreads();
        // Stage Vp chunk (128 rows x 128), XOR-quad swizzled
        #pragma unroll
        for (int it = 0; it < 16; it++) {
            int i = it * 1024 + tid * 4;
            int m = i >> 7, d = i & 127;
            float4 v = *(const float4*)&vpg[(size_t)ch * 16384 + i];
            *(float4*)&Vps[m * 128 + (d ^ (((m >> 2) & 7) << 2))] = v;
        }
        __syncthreads();

        ull acc[2][4];
        #pragma unroll
        for (int t = 0; t < 2; t++)
            #pragma unroll
            for (int j = 0; j < 4; j++) acc[t][j] = 0ULL;

        const float* uc0 = &Ucs[(2 * ng) * 128];
        const float* uc1 = &Ucs[(2 * ng + 1) * 128];
        #pragma unroll 4
        for (int d = 0; d < 128; d += 4) {
            ulonglong2 u0 = *(const ulonglong2*)&uc0[d];
            ulonglong2 u1 = *(const ulonglong2*)&uc1[d];
            const int dsw = d ^ swzS;
            #pragma unroll
            for (int j = 0; j < 4; j++) {
                ulonglong2 vv = *(const ulonglong2*)&Vps[(m0 + j) * 128 + dsw];
                acc[0][j] = ffma2(u0.x, vv.x, acc[0][j]);
                acc[0][j] = ffma2(u0.y, vv.y, acc[0][j]);
                acc[1][j] = ffma2(u1.x, vv.x, acc[1][j]);
                acc[1][j] = ffma2(u1.y, vv.y, acc[1][j]);
            }
        }
        #pragma unroll
        for (int t = 0; t < 2; t++) {
            float2 p0 = unpack2(acc[t][0]);
            float2 p1 = unpack2(acc[t][1]);
            float2 p2 = unpack2(acc[t][2]);
            float2 p3 = unpack2(acc[t][3]);
            *(float4*)&S[(2 * ng + t) * 1024 + ch * 128 + m0] =
                make_float4(p0.x + p0.y, p1.x + p1.y, p2.x + p2.y, p3.x + p3.y);
        }
    }
    __syncthreads();

    // ---------------- Phase 2: softmax (exp kept unnormalized; 1/sum saved) ----
    {
        const int w = tid >> 5, lane = tid & 31;
        #pragma unroll
        for (int t = 0; t < 2; t++) {
            int row = 2 * w + t;
            float* sr = &S[row * 1024];
            float mx = -1e30f;
            #pragma unroll
            for (int k = 0; k < 32; k++) mx = fmaxf(mx, sr[k * 32 + lane]);
            #pragma unroll
            for (int off = 16; off; off >>= 1)
                mx = fmaxf(mx, __shfl_xor_sync(0xffffffffu, mx, off));
            float sum = 0.0f;
            #pragma unroll
            for (int k = 0; k < 32; k++) {
                float e = __expf(sr[k * 32 + lane] - mx);
                sr[k * 32 + lane] = e;
                sum += e;
            }
            #pragma unroll
            for (int off = 16; off; off >>= 1)
                sum += __shfl_xor_sync(0xffffffffu, sum, off);
            if (lane == 0) invl[row] = 1.0f / sum;
        }
    }

    // ---------------- Phase 3: context ----------------
    const int dq = tid & 31, ng2 = tid >> 5;       // warp = one ng2 (2 n-rows)
    const int d0 = dq * 4;
    ull cacc[2][2];
    cacc[0][0] = cacc[0][1] = cacc[1][0] = cacc[1][1] = 0ULL;

    for (int ch = 0; ch < 8; ch++) {
        __syncthreads();
        #pragma unroll
        for (int it = 0; it < 16; it++) {
            int i = it * 1024 + tid * 4;
            int m = i >> 7, d = i & 127;
            float4 v = *(const float4*)&vpg[(size_t)ch * 16384 + i];
            *(float4*)&Vps[m * 128 + (d ^ (((m >> 2) & 7) << 2))] = v;
        }
        __syncthreads();

        const float* s0 = &S[(2 * ng2) * 1024 + ch * 128];
        const float* s1 = s0 + 1024;
        #pragma unroll 4
        for (int mm = 0; mm < 128; mm++) {
            ulonglong2 vv =
                *(const ulonglong2*)&Vps[mm * 128 + (d0 ^ (((mm >> 2) & 7) << 2))];
            float w0f = s0[mm], w1f = s1[mm];
            ull w0 = pack2(w0f, w0f);
            ull w1 = pack2(w1f, w1f);
            cacc[0][0] = ffma2(w0, vv.x, cacc[0][0]);
            cacc[0][1] = ffma2(w0, vv.y, cacc[0][1]);
            cacc[1][0] = ffma2(w1, vv.x, cacc[1][0]);
            cacc[1][1] = ffma2(w1, vv.y, cacc[1][1]);
        }
    }

    // ---------------- Epilogue: sum over the 16 n-rows ----------------
    float j0 = 0.f, j1 = 0.f, j2 = 0.f, j3 = 0.f;
    #pragma unroll
    for (int t = 0; t < 2; t++) {
        const int n = 2 * ng2 + t;
        const float il = invl[n];
        float4 uc = *(const float4*)&Ucs[n * 128 + d0];
        float2 a = unpack2(cacc[t][0]);
        float2 c = unpack2(cacc[t][1]);
        j0 += uc.x + a.x * il;
        j1 += uc.y + a.y * il;
        j2 += uc.z + c.x * il;
        j3 += uc.w + c.y * il;
    }
    atomicAdd(&ppart[d0 + 0], j0);
    atomicAdd(&ppart[d0 + 1], j1);
    atomicAdd(&ppart[d0 + 2], j2);
    atomicAdd(&ppart[d0 + 3], j3);
    __syncthreads();
    if (tid < 128)
        part[(size_t)blockIdx.x * D_ + tid] = ppart[tid];
}

// ============================================================================
// Final reduce: out[b][d] = (q[d]/N) * sum_{nt} part[b][nt][d]
// ============================================================================
__global__ __launch_bounds__(256)
void reduce_kernel(const float* __restrict__ part, const float* __restrict__ q,
                   float* __restrict__ out) {
    int i = blockIdx.x * blockDim.x + threadIdx.x;
    int b = i >> 7, d = i & 127;
    float s = 0.0f;
    #pragma unroll
    for (int nt = 0; nt < 32; nt++)
        s += part[(size_t)((b << 5) + nt) * D_ + d];
    out[i] = s * q[d] * (1.0f / (float)N_);
}

// ============================================================================
extern "C" void kernel_launch(void* const* d_in, const int* in_sizes, int n_in,
                              void* d_out, int out_size) {
    const float* h_c = (const float*)d_in[0];
    const float* h_p = (const float*)d_in[1];
    const float* U_w = (const float*)d_in[2];
    const float* U_b = (const float*)d_in[3];
    const float* V_w = (const float*)d_in[4];
    const float* V_b = (const float*)d_in[5];
    const float* q   = (const float*)d_in[6];
    float* out = (float*)d_out;

    void *pUc, *pVp, *pPart;
    cudaGetSymbolAddress(&pUc, g_Uc);
    cudaGetSymbolAddress(&pVp, g_Vp);
    cudaGetSymbolAddress(&pPart, g_part);

    const int PROJ_SMEM = (16384 + 64 * 132) * 4;   // 99328 B
    const int ATTN_SMEM = 34960 * 4;                // 139840 B
    cudaFuncSetAttribute(proj_kernel,
                         cudaFuncAttributeMaxDynamicSharedMemorySize, PROJ_SMEM);
    cudaFuncSetAttribute(attn_kernel,
                         cudaFuncAttributeMaxDynamicSharedMemorySize, ATTN_SMEM);

    proj_kernel<<<(B_ * N_) / 64, 256, PROJ_SMEM>>>(h_c, U_w, U_b, (float*)pUc);
    proj_kernel<<<(B_ * M_) / 64, 256, PROJ_SMEM>>>(h_p, V_w, V_b, (float*)pVp);
    attn_kernel<<<B_ * 32, 256, ATTN_SMEM>>>((const float*)pUc,
                                             (const float*)pVp, (float*)pPart);
    reduce_kernel<<<(B_ * D_) / 256, 256>>>((const float*)pPart, q, out);
}

// round 5
// speedup vs baseline: 3.0060x; 2.9957x over previous
#include <cuda_runtime.h>
#include <cuda_bf16.h>
#include <cstdint>

#define B_ 64
#define N_ 512
#define M_ 1024
#define D_ 128

typedef unsigned long long ull;

extern __shared__ char dynsm[];

// ---------------- device scratch (allocation-free) ----------------
__device__ __nv_bfloat16 g_UcHi[(size_t)B_ * N_ * D_];
__device__ __nv_bfloat16 g_UcLo[(size_t)B_ * N_ * D_];
__device__ __nv_bfloat16 g_VpHi[(size_t)B_ * M_ * D_];
__device__ __nv_bfloat16 g_VpLo[(size_t)B_ * M_ * D_];
__device__ __nv_bfloat16 g_VtHi[(size_t)B_ * D_ * M_];   // [b][d][m]
__device__ __nv_bfloat16 g_VtLo[(size_t)B_ * D_ * M_];
__device__ float g_part[(size_t)B_ * 8 * D_];

// ---------------- helpers ----------------
__device__ __forceinline__ ull ffma2(ull a, ull b, ull c) {
    ull d; asm("fma.rn.f32x2 %0, %1, %2, %3;" : "=l"(d) : "l"(a), "l"(b), "l"(c));
    return d;
}
__device__ __forceinline__ float2 unpack2(ull v) {
    float2 f; asm("mov.b64 {%0, %1}, %2;" : "=f"(f.x), "=f"(f.y) : "l"(v)); return f;
}
// d[31:16] = bf16(hi), d[15:0] = bf16(lo)
__device__ __forceinline__ uint32_t pack_bf16x2(float hi, float lo) {
    uint32_t r;
    asm("cvt.rn.bf16x2.f32 %0, %1, %2;" : "=r"(r) : "f"(hi), "f"(lo));
    return r;
}
__device__ __forceinline__ float lo_f(uint32_t p) { return __uint_as_float(p << 16); }
__device__ __forceinline__ float hi_f(uint32_t p) { return __uint_as_float(p & 0xffff0000u); }

__device__ __forceinline__ void mma_bf16(float* c, uint32_t a0, uint32_t a1,
                                         uint32_t a2, uint32_t a3,
                                         uint32_t b0, uint32_t b1) {
    asm volatile(
        "mma.sync.aligned.m16n8k16.row.col.f32.bf16.bf16.f32 "
        "{%0,%1,%2,%3},{%4,%5,%6,%7},{%8,%9},{%0,%1,%2,%3};"
        : "+f"(c[0]), "+f"(c[1]), "+f"(c[2]), "+f"(c[3])
        : "r"(a0), "r"(a1), "r"(a2), "r"(a3), "r"(b0), "r"(b1));
}

// ============================================================================
// Projection: relu(X @ W^T + b), fp32 FFMA2 core, bf16 hi/lo outputs
// ============================================================================
__global__ __launch_bounds__(256)
void proj_kernel(const float* __restrict__ X, const float* __restrict__ W,
                 const float* __restrict__ bias,
                 __nv_bfloat16* __restrict__ outHi,
                 __nv_bfloat16* __restrict__ outLo) {
    float* sm = (float*)dynsm;
    float* Ws = sm;
    float* Xs = sm + 16384;
    const int tid = threadIdx.x;
    const size_t row0 = (size_t)blockIdx.x * 64;

    #pragma unroll
    for (int it = 0; it < 16; it++) {
        int i = it * 1024 + tid * 4;
        int c = i >> 7, d = i & 127;
        float4 v = *(const float4*)&W[i];
        *(float4*)&Ws[c * 128 + (d ^ (((c >> 3) & 7) << 2))] = v;
    }
    #pragma unroll
    for (int it = 0; it < 8; it++) {
        int i = it * 1024 + tid * 4;
        int r = i >> 7, d = i & 127;
        *(float4*)&Xs[r * 132 + d] = *(const float4*)&X[row0 * D_ + i];
    }
    __syncthreads();

    const int cg = tid & 15, rg = tid >> 4;
    const int r0 = rg * 4, c0 = cg * 8;
    const int swz = (cg & 7) << 2;

    ull acc[4][8];
    #pragma unroll
    for (int i = 0; i < 4; i++)
        #pragma unroll
        for (int j = 0; j < 8; j++) acc[i][j] = 0ULL;

    #pragma unroll 2
    for (int d = 0; d < 128; d += 4) {
        ulonglong2 x[4];
        #pragma unroll
        for (int i = 0; i < 4; i++)
            x[i] = *(const ulonglong2*)&Xs[(r0 + i) * 132 + d];
        const int dsw = d ^ swz;
        #pragma unroll
        for (int j = 0; j < 8; j++) {
            ulonglong2 wv = *(const ulonglong2*)&Ws[(c0 + j) * 128 + dsw];
            #pragma unroll
            for (int i = 0; i < 4; i++) {
                acc[i][j] = ffma2(x[i].x, wv.x, acc[i][j]);
                acc[i][j] = ffma2(x[i].y, wv.y, acc[i][j]);
            }
        }
    }
    #pragma unroll
    for (int i = 0; i < 4; i++) {
        float o[8];
        #pragma unroll
        for (int j = 0; j < 8; j++) {
            float2 p = unpack2(acc[i][j]);
            o[j] = fmaxf(p.x + p.y + bias[c0 + j], 0.0f);
        }
        uint32_t hw[4], lw[4];
        #pragma unroll
        for (int jj = 0; jj < 4; jj++) {
            float o0 = o[2 * jj], o1 = o[2 * jj + 1];
            uint32_t h = pack_bf16x2(o1, o0);
            hw[jj] = h;
            lw[jj] = pack_bf16x2(o1 - hi_f(h), o0 - lo_f(h));
        }
        size_t go = (row0 + r0 + i) * (size_t)D_ + c0;
        *(uint4*)(outHi + go) = make_uint4(hw[0], hw[1], hw[2], hw[3]);
        *(uint4*)(outLo + go) = make_uint4(lw[0], lw[1], lw[2], lw[3]);
    }
}

// ============================================================================
// Transpose Vp[b][m][d] -> Vt[b][d][m] (hi+lo), 64x64 bf16 tiles
// ============================================================================
__global__ __launch_bounds__(256)
void trans_kernel(const __nv_bfloat16* __restrict__ inH,
                  const __nv_bfloat16* __restrict__ inL,
                  __nv_bfloat16* __restrict__ outH,
                  __nv_bfloat16* __restrict__ outL) {
    __shared__ unsigned short Th[64 * 65], Tl[64 * 65];
    const int blk = blockIdx.x;
    const int b = blk >> 5, mt = (blk >> 1) & 15, dt = blk & 1;
    const int m0 = mt * 64, d0 = dt * 64;
    const int tid = threadIdx.x;

    #pragma unroll
    for (int it = 0; it < 2; it++) {
        int i = it * 256 + tid;
        int r = i >> 3, c8 = (i & 7) * 8;
        size_t gi = ((size_t)(b * 1024 + m0 + r)) * 128 + d0 + c8;
        unsigned short sh[8], sl[8];
        *(uint4*)sh = *(const uint4*)(inH + gi);
        *(uint4*)sl = *(const uint4*)(inL + gi);
        #pragma unroll
        for (int k = 0; k < 8; k++) {
            Th[r * 65 + c8 + k] = sh[k];
            Tl[r * 65 + c8 + k] = sl[k];
        }
    }
    __syncthreads();
    #pragma unroll
    for (int it = 0; it < 2; it++) {
        int i = it * 256 + tid;
        int c = i >> 3, r8 = (i & 7) * 8;
        unsigned short sh[8], sl[8];
        #pragma unroll
        for (int k = 0; k < 8; k++) {
            sh[k] = Th[(r8 + k) * 65 + c];
            sl[k] = Tl[(r8 + k) * 65 + c];
        }
        size_t go = ((size_t)(b * 128 + d0 + c)) * 1024 + m0 + r8;
        *(uint4*)(outH + go) = *(uint4*)sh;
        *(uint4*)(outL + go) = *(uint4*)sl;
    }
}

// ============================================================================
// Fused attention via mma.sync (bf16 split). CTA = (b, 64 n-rows), 256 thr.
// Warp grid 4(n) x 2(m/d). 16 m-chunks of 64. Softmax with fixed shift C=40
// (logits >= 0 since ReLU'd operands; no max pass needed).
// ============================================================================
// byte offsets
#define OFF_UCH 0
#define OFF_UCL 17408
#define OFF_VH  34816
#define OFF_VL  52224
#define OFF_TH  69632
#define OFF_TL  88064
#define OFF_PH  106496
#define OFF_PL  115712
#define OFF_RS  124928
#define OFF_INV 125440
#define OFF_RED 125696
#define ATTN_SMEM 126720

__global__ __launch_bounds__(256, 1)
void attn_kernel(float* __restrict__ part) {
    char* sm = dynsm;
    const int tid = threadIdx.x, wid = tid >> 5, lane = tid & 31;
    const int wr = wid & 3, wc = wid >> 2;
    const int g = lane >> 2, t = lane & 3;
    const int b = blockIdx.x >> 3, nt = blockIdx.x & 7;

    uint32_t* UC32h = (uint32_t*)(sm + OFF_UCH);   // stride 68 u32 per row
    uint32_t* UC32l = (uint32_t*)(sm + OFF_UCL);
    uint32_t* V32h  = (uint32_t*)(sm + OFF_VH);    // stride 68
    uint32_t* V32l  = (uint32_t*)(sm + OFF_VL);
    uint32_t* T32h  = (uint32_t*)(sm + OFF_TH);    // stride 36
    uint32_t* T32l  = (uint32_t*)(sm + OFF_TL);
    uint32_t* P32h  = (uint32_t*)(sm + OFF_PH);    // stride 36
    uint32_t* P32l  = (uint32_t*)(sm + OFF_PL);
    float* RS  = (float*)(sm + OFF_RS);
    float* INV = (float*)(sm + OFF_INV);
    float* RED = (float*)(sm + OFF_RED);

    const uint4* ucHg = (const uint4*)(g_UcHi + ((size_t)(b * N_ + nt * 64)) * D_);
    const uint4* ucLg = (const uint4*)(g_UcLo + ((size_t)(b * N_ + nt * 64)) * D_);
    const uint4* vpHg = (const uint4*)(g_VpHi + (size_t)b * M_ * D_);
    const uint4* vpLg = (const uint4*)(g_VpLo + (size_t)b * M_ * D_);
    const uint4* vtHg = (const uint4*)(g_VtHi + (size_t)b * D_ * M_);
    const uint4* vtLg = (const uint4*)(g_VtLo + (size_t)b * D_ * M_);

    uint4* UH4 = (uint4*)(sm + OFF_UCH);
    uint4* UL4 = (uint4*)(sm + OFF_UCL);
    uint4* VH4 = (uint4*)(sm + OFF_VH);
    uint4* VL4 = (uint4*)(sm + OFF_VL);
    uint4* TH4 = (uint4*)(sm + OFF_TH);
    uint4* TL4 = (uint4*)(sm + OFF_TL);

    // stage Uc (64 rows x 128 = 1024 uint4 per buffer)
    #pragma unroll
    for (int it = 0; it < 4; it++) {
        int i = it * 256 + tid;
        int r = i >> 4, c = i & 15;
        UH4[r * 17 + c] = ucHg[i];
        UL4[r * 17 + c] = ucLg[i];
    }

    const int rA = 16 * wr + g;
    float cacc[8][4];
    #pragma unroll
    for (int j = 0; j < 8; j++)
        #pragma unroll
        for (int q = 0; q < 4; q++) cacc[j][q] = 0.0f;
    float rs0 = 0.0f, rs1 = 0.0f;

    for (int mc = 0; mc < 16; mc++) {
        // stage Vp chunk (64 x 128) and Vt chunk (128 x 64)
        #pragma unroll
        for (int it = 0; it < 4; it++) {
            int i = it * 256 + tid;
            int r = i >> 4, c = i & 15;
            VH4[r * 17 + c] = vpHg[(mc * 64 + r) * 16 + c];
            VL4[r * 17 + c] = vpLg[(mc * 64 + r) * 16 + c];
            int dR = i >> 3, m8 = i & 7;
            TH4[dR * 9 + m8] = vtHg[dR * 128 + mc * 8 + m8];
            TL4[dR * 9 + m8] = vtLg[dR * 128 + mc * 8 + m8];
        }
        __syncthreads();

        // ---- scores: 16n x 32m per warp, k=128 ----
        float acc[4][4];
        #pragma unroll
        for (int j = 0; j < 4; j++)
            #pragma unroll
            for (int q = 0; q < 4; q++) acc[j][q] = 0.0f;

        const uint32_t* Uh = UC32h + rA * 68 + t;
        const uint32_t* Ul = UC32l + rA * 68 + t;
        #pragma unroll
        for (int kk = 0; kk < 8; kk++) {
            const int ka = kk * 8;
            uint32_t ah0 = Uh[ka], ah1 = Uh[ka + 8 * 68];
            uint32_t ah2 = Uh[ka + 4], ah3 = Uh[ka + 8 * 68 + 4];
            uint32_t al0 = Ul[ka], al1 = Ul[ka + 8 * 68];
            uint32_t al2 = Ul[ka + 4], al3 = Ul[ka + 8 * 68 + 4];
            #pragma unroll
            for (int j = 0; j < 4; j++) {
                const int rB = (wc * 32 + j * 8 + g) * 68 + t;
                uint32_t bh0 = V32h[rB + ka], bh1 = V32h[rB + ka + 4];
                uint32_t bl0 = V32l[rB + ka], bl1 = V32l[rB + ka + 4];
                mma_bf16(acc[j], ah0, ah1, ah2, ah3, bh0, bh1);
                mma_bf16(acc[j], ah0, ah1, ah2, ah3, bl0, bl1);
                mma_bf16(acc[j], al0, al1, al2, al3, bh0, bh1);
            }
        }

        // ---- exp + rowsum + pack P (bf16 hi/lo) ----
        #pragma unroll
        for (int j = 0; j < 4; j++) {
            float e0 = __expf(acc[j][0] - 40.0f);
            float e1 = __expf(acc[j][1] - 40.0f);
            float e2 = __expf(acc[j][2] - 40.0f);
            float e3 = __expf(acc[j][3] - 40.0f);
            rs0 += e0 + e1;
            rs1 += e2 + e3;
            uint32_t h0 = pack_bf16x2(e1, e0);
            uint32_t l0 = pack_bf16x2(e1 - hi_f(h0), e0 - lo_f(h0));
            uint32_t h1 = pack_bf16x2(e3, e2);
            uint32_t l1 = pack_bf16x2(e3 - hi_f(h1), e2 - lo_f(h1));
            const int pc = wc * 16 + 4 * j + t;
            P32h[rA * 36 + pc] = h0;
            P32l[rA * 36 + pc] = l0;
            P32h[(rA + 8) * 36 + pc] = h1;
            P32l[(rA + 8) * 36 + pc] = l1;
        }
        __syncthreads();

        // ---- ctx: 16n x 64d per warp, k=64 ----
        const uint32_t* Ph = P32h + rA * 36 + t;
        const uint32_t* Pl = P32l + rA * 36 + t;
        #pragma unroll
        for (int kk = 0; kk < 4; kk++) {
            const int ka = kk * 8;
            uint32_t ph0 = Ph[ka], ph1 = Ph[ka + 8 * 36];
            uint32_t ph2 = Ph[ka + 4], ph3 = Ph[ka + 8 * 36 + 4];
            uint32_t pl0 = Pl[ka], pl1 = Pl[ka + 8 * 36];
            uint32_t pl2 = Pl[ka + 4], pl3 = Pl[ka + 8 * 36 + 4];
            #pragma unroll
            for (int j = 0; j < 8; j++) {
                const int rB = (64 * wc + j * 8 + g) * 36 + t;
                uint32_t bh0 = T32h[rB + ka], bh1 = T32h[rB + ka + 4];
                uint32_t bl0 = T32l[rB + ka], bl1 = T32l[rB + ka + 4];
                mma_bf16(cacc[j], ph0, ph1, ph2, ph3, bh0, bh1);
                mma_bf16(cacc[j], pl0, pl1, pl2, pl3, bh0, bh1);
                mma_bf16(cacc[j], ph0, ph1, ph2, ph3, bl0, bl1);
            }
        }
        __syncthreads();
    }

    // ---- row sums -> inverse ----
    rs0 += __shfl_xor_sync(0xffffffffu, rs0, 1);
    rs0 += __shfl_xor_sync(0xffffffffu, rs0, 2);
    rs1 += __shfl_xor_sync(0xffffffffu, rs1, 1);
    rs1 += __shfl_xor_sync(0xffffffffu, rs1, 2);
    if (t == 0) {
        RS[wc * 64 + rA] = rs0;
        RS[wc * 64 + rA + 8] = rs1;
    }
    __syncthreads();
    if (tid < 64) INV[tid] = 1.0f / (RS[tid] + RS[64 + tid]);
    __syncthreads();

    // ---- epilogue: joint = Uc + ctx/l, write Jt, reduce over n ----
    const float iA = INV[rA], iB = INV[rA + 8];
    float* Jt = (float*)(sm + OFF_VH);   // 64 x 132 f32 (reuses V area)
    #pragma unroll
    for (int j = 0; j < 8; j++) {
        const int d0 = 64 * wc + j * 8 + 2 * t;
        uint32_t uh = UC32h[rA * 68 + (d0 >> 1)];
        uint32_t ul = UC32l[rA * 68 + (d0 >> 1)];
        Jt[rA * 132 + d0]     = lo_f(uh) + lo_f(ul) + cacc[j][0] * iA;
        Jt[rA * 132 + d0 + 1] = hi_f(uh) + hi_f(ul) + cacc[j][1] * iA;
        uint32_t uh2 = UC32h[(rA + 8) * 68 + (d0 >> 1)];
        uint32_t ul2 = UC32l[(rA + 8) * 68 + (d0 >> 1)];
        Jt[(rA + 8) * 132 + d0]     = lo_f(uh2) + lo_f(ul2) + cacc[j][2] * iB;
        Jt[(rA + 8) * 132 + d0 + 1] = hi_f(uh2) + hi_f(ul2) + cacc[j][3] * iB;
    }
    __syncthreads();
    {
        int h = tid >> 7, d = tid & 127;
        float s = 0.0f;
        #pragma unroll
        for (int r = 0; r < 32; r++) s += Jt[(h * 32 + r) * 132 + d];
        RED[h * 128 + d] = s;
    }
    __syncthreads();
    if (tid < 128)
        part[(size_t)blockIdx.x * D_ + tid] = RED[tid] + RED[128 + tid];
}

// ============================================================================
__global__ __launch_bounds__(256)
void reduce_kernel(const float* __restrict__ part, const float* __restrict__ q,
                   float* __restrict__ out) {
    int i = blockIdx.x * blockDim.x + threadIdx.x;
    int b = i >> 7, d = i & 127;
    float s = 0.0f;
    #pragma unroll
    for (int nt = 0; nt < 8; nt++)
        s += part[(size_t)(b * 8 + nt) * D_ + d];
    out[i] = s * q[d] * (1.0f / (float)N_);
}

// ============================================================================
extern "C" void kernel_launch(void* const* d_in, const int* in_sizes, int n_in,
                              void* d_out, int out_size) {
    const float* h_c = (const float*)d_in[0];
    const float* h_p = (const float*)d_in[1];
    const float* U_w = (const float*)d_in[2];
    const float* U_b = (const float*)d_in[3];
    const float* V_w = (const float*)d_in[4];
    const float* V_b = (const float*)d_in[5];
    const float* q   = (const float*)d_in[6];
    float* out = (float*)d_out;

    void *pUcH, *pUcL, *pVpH, *pVpL, *pVtH, *pVtL, *pPart;
    cudaGetSymbolAddress(&pUcH, g_UcHi);
    cudaGetSymbolAddress(&pUcL, g_UcLo);
    cudaGetSymbolAddress(&pVpH, g_VpHi);
    cudaGetSymbolAddress(&pVpL, g_VpLo);
    cudaGetSymbolAddress(&pVtH, g_VtHi);
    cudaGetSymbolAddress(&pVtL, g_VtLo);
    cudaGetSymbolAddress(&pPart, g_part);

    const int PROJ_SMEM = (16384 + 64 * 132) * 4;
    cudaFuncSetAttribute(proj_kernel,
                         cudaFuncAttributeMaxDynamicSharedMemorySize, PROJ_SMEM);
    cudaFuncSetAttribute(attn_kernel,
                         cudaFuncAttributeMaxDynamicSharedMemorySize, ATTN_SMEM);

    proj_kernel<<<(B_ * N_) / 64, 256, PROJ_SMEM>>>(
        h_c, U_w, U_b, (__nv_bfloat16*)pUcH, (__nv_bfloat16*)pUcL);
    proj_kernel<<<(B_ * M_) / 64, 256, PROJ_SMEM>>>(
        h_p, V_w, V_b, (__nv_bfloat16*)pVpH, (__nv_bfloat16*)pVpL);
    trans_kernel<<<2048, 256>>>((const __nv_bfloat16*)pVpH,
                                (const __nv_bfloat16*)pVpL,
                                (__nv_bfloat16*)pVtH, (__nv_bfloat16*)pVtL);
    attn_kernel<<<B_ * 8, 256, ATTN_SMEM>>>((float*)pPart);
    reduce_kernel<<<(B_ * D_) / 256, 256>>>((const float*)pPart, q, out);
}

// round 7
// speedup vs baseline: 3.1124x; 1.0354x over previous
#include <cuda_runtime.h>
#include <cuda_bf16.h>
#include <cstdint>

#define B_ 64
#define N_ 512
#define M_ 1024
#define D_ 128

typedef unsigned long long ull;

extern __shared__ char dynsm[];

// ---------------- device scratch (allocation-free) ----------------
__device__ __nv_bfloat16 g_UcHi[(size_t)B_ * N_ * D_];
__device__ __nv_bfloat16 g_UcLo[(size_t)B_ * N_ * D_];
__device__ __nv_bfloat16 g_VpHi[(size_t)B_ * M_ * D_];
__device__ __nv_bfloat16 g_VpLo[(size_t)B_ * M_ * D_];
__device__ __nv_bfloat16 g_VtHi[(size_t)B_ * D_ * M_];   // [b][d][m]
__device__ __nv_bfloat16 g_VtLo[(size_t)B_ * D_ * M_];
__device__ float g_part[(size_t)B_ * 8 * D_];

// ---------------- helpers ----------------
__device__ __forceinline__ ull ffma2(ull a, ull b, ull c) {
    ull d; asm("fma.rn.f32x2 %0, %1, %2, %3;" : "=l"(d) : "l"(a), "l"(b), "l"(c));
    return d;
}
__device__ __forceinline__ float2 unpack2(ull v) {
    float2 f; asm("mov.b64 {%0, %1}, %2;" : "=f"(f.x), "=f"(f.y) : "l"(v)); return f;
}
__device__ __forceinline__ uint32_t pack_bf16x2(float hi, float lo) {
    uint32_t r;
    asm("cvt.rn.bf16x2.f32 %0, %1, %2;" : "=r"(r) : "f"(hi), "f"(lo));
    return r;
}
__device__ __forceinline__ float lo_f(uint32_t p) { return __uint_as_float(p << 16); }
__device__ __forceinline__ float hi_f(uint32_t p) { return __uint_as_float(p & 0xffff0000u); }

__device__ __forceinline__ uint32_t smem_u32(const void* p) {
    uint32_t a;
    asm("{ .reg .u64 t; cvta.to.shared.u64 t, %1; cvt.u32.u64 %0, t; }"
        : "=r"(a) : "l"(p));
    return a;
}
__device__ __forceinline__ void mma_bf16(float* c, uint32_t a0, uint32_t a1,
                                         uint32_t a2, uint32_t a3,
                                         uint32_t b0, uint32_t b1) {
    asm volatile(
        "mma.sync.aligned.m16n8k16.row.col.f32.bf16.bf16.f32 "
        "{%0,%1,%2,%3},{%4,%5,%6,%7},{%8,%9},{%0,%1,%2,%3};"
        : "+f"(c[0]), "+f"(c[1]), "+f"(c[2]), "+f"(c[3])
        : "r"(a0), "r"(a1), "r"(a2), "r"(a3), "r"(b0), "r"(b1));
}
__device__ __forceinline__ void ldsm_x4(uint32_t& r0, uint32_t& r1, uint32_t& r2,
                                        uint32_t& r3, uint32_t addr) {
    asm volatile("ldmatrix.sync.aligned.m8n8.x4.shared.b16 {%0,%1,%2,%3}, [%4];"
                 : "=r"(r0), "=r"(r1), "=r"(r2), "=r"(r3) : "r"(addr));
}
__device__ __forceinline__ void ldsm_x2(uint32_t& r0, uint32_t& r1, uint32_t addr) {
    asm volatile("ldmatrix.sync.aligned.m8n8.x2.shared.b16 {%0,%1}, [%2];"
                 : "=r"(r0), "=r"(r1) : "r"(addr));
}
__device__ __forceinline__ void cpa16(uint32_t dst, const void* src) {
    asm volatile("cp.async.cg.shared.global [%0], [%1], 16;"
                 :: "r"(dst), "l"(src) : "memory");
}
#define CP_COMMIT() asm volatile("cp.async.commit_group;" ::: "memory")
#define CP_WAIT1() asm volatile("cp.async.wait_group 1;" ::: "memory")
#define CP_WAIT0() asm volatile("cp.async.wait_group 0;" ::: "memory")

// ============================================================================
// Projection: relu(X @ W^T + b), fp32 FFMA2 core, bf16 hi/lo outputs
// ============================================================================
__global__ __launch_bounds__(256)
void proj_kernel(const float* __restrict__ X, const float* __restrict__ W,
                 const float* __restrict__ bias,
                 __nv_bfloat16* __restrict__ outHi,
                 __nv_bfloat16* __restrict__ outLo) {
    float* sm = (float*)dynsm;
    float* Ws = sm;
    float* Xs = sm + 16384;
    const int tid = threadIdx.x;
    const size_t row0 = (size_t)blockIdx.x * 64;

    #pragma unroll
    for (int it = 0; it < 16; it++) {
        int i = it * 1024 + tid * 4;
        int c = i >> 7, d = i & 127;
        float4 v = *(const float4*)&W[i];
        *(float4*)&Ws[c * 128 + (d ^ (((c >> 3) & 7) << 2))] = v;
    }
    #pragma unroll
    for (int it = 0; it < 8; it++) {
        int i = it * 1024 + tid * 4;
        int r = i >> 7, d = i & 127;
        *(float4*)&Xs[r * 132 + d] = *(const float4*)&X[row0 * D_ + i];
    }
    __syncthreads();

    const int cg = tid & 15, rg = tid >> 4;
    const int r0 = rg * 4, c0 = cg * 8;
    const int swz = (cg & 7) << 2;

    ull acc[4][8];
    #pragma unroll
    for (int i = 0; i < 4; i++)
        #pragma unroll
        for (int j = 0; j < 8; j++) acc[i][j] = 0ULL;

    #pragma unroll 2
    for (int d = 0; d < 128; d += 4) {
        ulonglong2 x[4];
        #pragma unroll
        for (int i = 0; i < 4; i++)
            x[i] = *(const ulonglong2*)&Xs[(r0 + i) * 132 + d];
        const int dsw = d ^ swz;
        #pragma unroll
        for (int j = 0; j < 8; j++) {
            ulonglong2 wv = *(const ulonglong2*)&Ws[(c0 + j) * 128 + dsw];
            #pragma unroll
            for (int i = 0; i < 4; i++) {
                acc[i][j] = ffma2(x[i].x, wv.x, acc[i][j]);
                acc[i][j] = ffma2(x[i].y, wv.y, acc[i][j]);
            }
        }
    }
    #pragma unroll
    for (int i = 0; i < 4; i++) {
        float o[8];
        #pragma unroll
        for (int j = 0; j < 8; j++) {
            float2 p = unpack2(acc[i][j]);
            o[j] = fmaxf(p.x + p.y + bias[c0 + j], 0.0f);
        }
        uint32_t hw[4], lw[4];
        #pragma unroll
        for (int jj = 0; jj < 4; jj++) {
            float o0 = o[2 * jj], o1 = o[2 * jj + 1];
            uint32_t h = pack_bf16x2(o1, o0);
            hw[jj] = h;
            lw[jj] = pack_bf16x2(o1 - hi_f(h), o0 - lo_f(h));
        }
        size_t go = (row0 + r0 + i) * (size_t)D_ + c0;
        *(uint4*)(outHi + go) = make_uint4(hw[0], hw[1], hw[2], hw[3]);
        *(uint4*)(outLo + go) = make_uint4(lw[0], lw[1], lw[2], lw[3]);
    }
}

// ============================================================================
// Transpose Vp[b][m][d] -> Vt[b][d][m] (hi+lo), 64x64 bf16 tiles
// ============================================================================
__global__ __launch_bounds__(256)
void trans_kernel(const __nv_bfloat16* __restrict__ inH,
                  const __nv_bfloat16* __restrict__ inL,
                  __nv_bfloat16* __restrict__ outH,
                  __nv_bfloat16* __restrict__ outL) {
    __shared__ unsigned short Th[64 * 65], Tl[64 * 65];
    const int blk = blockIdx.x;
    const int b = blk >> 5, mt = (blk >> 1) & 15, dt = blk & 1;
    const int m0 = mt * 64, d0 = dt * 64;
    const int tid = threadIdx.x;

    #pragma unroll
    for (int it = 0; it < 2; it++) {
        int i = it * 256 + tid;
        int r = i >> 3, c8 = (i & 7) * 8;
        size_t gi = ((size_t)(b * 1024 + m0 + r)) * 128 + d0 + c8;
        unsigned short sh[8], sl[8];
        *(uint4*)sh = *(const uint4*)(inH + gi);
        *(uint4*)sl = *(const uint4*)(inL + gi);
        #pragma unroll
        for (int k = 0; k < 8; k++) {
            Th[r * 65 + c8 + k] = sh[k];
            Tl[r * 65 + c8 + k] = sl[k];
        }
    }
    __syncthreads();
    #pragma unroll
    for (int it = 0; it < 2; it++) {
        int i = it * 256 + tid;
        int c = i >> 3, r8 = (i & 7) * 8;
        unsigned short sh[8], sl[8];
        #pragma unroll
        for (int k = 0; k < 8; k++) {
            sh[k] = Th[(r8 + k) * 65 + c];
            sl[k] = Tl[(r8 + k) * 65 + c];
        }
        size_t go = ((size_t)(b * 128 + d0 + c)) * 1024 + m0 + r8;
        *(uint4*)(outH + go) = *(uint4*)sh;
        *(uint4*)(outL + go) = *(uint4*)sl;
    }
}

// ============================================================================
// Fused attention: mma.sync bf16-split + ldmatrix + cp.async double buffering.
// CTA = (b, 64 n-rows), 256 thr, warp grid 4(n) x 2(m/d), 16 m-chunks of 64.
// ============================================================================
#define OFF_UCH 0
#define OFF_UCL 17408
#define OFF_VH0 34816
#define OFF_VL0 52224
#define OFF_VH1 69632
#define OFF_VL1 87040
#define OFF_TH0 104448
#define OFF_TL0 122880
#define OFF_TH1 141312
#define OFF_TL1 159744
#define OFF_PH  178176
#define OFF_PL  187392
#define OFF_RS  196608
#define OFF_INV 197120
#define OFF_RED 197376
#define ATTN_SMEM 198400

__global__ __launch_bounds__(256, 1)
void attn_kernel(float* __restrict__ part) {
    char* sm = dynsm;
    const uint32_t smu = smem_u32(sm);
    const int tid = threadIdx.x, wid = tid >> 5, lane = tid & 31;
    const int wr = wid & 3, wc = wid >> 2;
    const int g = lane >> 2, t = lane & 3;
    const int b = blockIdx.x >> 3, nt = blockIdx.x & 7;

    uint32_t* UC32h = (uint32_t*)(sm + OFF_UCH);   // stride 68 u32 per row
    uint32_t* UC32l = (uint32_t*)(sm + OFF_UCL);
    uint32_t* P32h  = (uint32_t*)(sm + OFF_PH);    // stride 36
    uint32_t* P32l  = (uint32_t*)(sm + OFF_PL);
    float* RS  = (float*)(sm + OFF_RS);
    float* INV = (float*)(sm + OFF_INV);
    float* RED = (float*)(sm + OFF_RED);

    const uint4* ucHg = (const uint4*)(g_UcHi + ((size_t)(b * N_ + nt * 64)) * D_);
    const uint4* ucLg = (const uint4*)(g_UcLo + ((size_t)(b * N_ + nt * 64)) * D_);
    const uint4* vpHg = (const uint4*)(g_VpHi + (size_t)b * M_ * D_);
    const uint4* vpLg = (const uint4*)(g_VpLo + (size_t)b * M_ * D_);
    const uint4* vtHg = (const uint4*)(g_VtHi + (size_t)b * D_ * M_);
    const uint4* vtLg = (const uint4*)(g_VtLo + (size_t)b * D_ * M_);

    // stage Uc (64 rows x 16 uint4 per buffer)
    uint4* UH4 = (uint4*)(sm + OFF_UCH);
    uint4* UL4 = (uint4*)(sm + OFF_UCL);
    #pragma unroll
    for (int it = 0; it < 4; it++) {
        int i = it * 256 + tid;
        int r = i >> 4, c = i & 15;
        UH4[r * 17 + c] = ucHg[i];
        UL4[r * 17 + c] = ucLg[i];
    }

    const uint32_t vhB[2] = {smu + OFF_VH0, smu + OFF_VH1};
    const uint32_t vlB[2] = {smu + OFF_VL0, smu + OFF_VL1};
    const uint32_t thB[2] = {smu + OFF_TH0, smu + OFF_TH1};
    const uint32_t tlB[2] = {smu + OFF_TL0, smu + OFF_TL1};

    // per-lane ldmatrix address components
    const int l7 = lane & 7, l8 = (lane >> 3) & 1, l16 = lane >> 4;
    // A (scores/Uc): rows 16wr..+16, x4
    const uint32_t aoffH = smu + OFF_UCH + ((16 * wr + l7 + l8 * 8) * 68 + l16 * 4) * 4;
    const uint32_t aoffL = smu + OFF_UCL + ((16 * wr + l7 + l8 * 8) * 68 + l16 * 4) * 4;
    // B (scores/V): rows wc*32+j*8..+8, x2 (lanes 0..15 meaningful)
    const uint32_t boffV = ((wc * 32 + l7) * 68 + l8 * 4) * 4;
    // A (ctx/P): rows 16wr..+16, x4, stride 36
    const uint32_t poffH = smu + OFF_PH + ((16 * wr + l7 + l8 * 8) * 36 + l16 * 4) * 4;
    const uint32_t poffL = smu + OFF_PL + ((16 * wr + l7 + l8 * 8) * 36 + l16 * 4) * 4;
    // B (ctx/T): rows 64wc+j*8..+8, x2, stride 36
    const uint32_t boffT = ((64 * wc + l7) * 36 + l8 * 4) * 4;

    const int rA = 16 * wr + g;
    float cacc[8][4];
    #pragma unroll
    for (int j = 0; j < 8; j++)
        #pragma unroll
        for (int q = 0; q < 4; q++) cacc[j][q] = 0.0f;
    float rs0 = 0.0f, rs1 = 0.0f;

    // stage chunk 0
    #pragma unroll
    for (int it = 0; it < 4; it++) {
        int i = it * 256 + tid;
        int r = i >> 4, c = i & 15;
        cpa16(vhB[0] + (r * 68 + c * 4) * 4, vpHg + r * 16 + c);
        cpa16(vlB[0] + (r * 68 + c * 4) * 4, vpLg + r * 16 + c);
        int dR = i >> 3, m8 = i & 7;
        cpa16(thB[0] + (dR * 36 + m8 * 4) * 4, vtHg + dR * 128 + m8);
        cpa16(tlB[0] + (dR * 36 + m8 * 4) * 4, vtLg + dR * 128 + m8);
    }
    CP_COMMIT();

    for (int mc = 0; mc < 16; mc++) {
        const int s = mc & 1;
        if (mc + 1 < 16) {
            const int s2 = (mc + 1) & 1;
            #pragma unroll
            for (int it = 0; it < 4; it++) {
                int i = it * 256 + tid;
                int r = i >> 4, c = i & 15;
                cpa16(vhB[s2] + (r * 68 + c * 4) * 4,
                      vpHg + ((mc + 1) * 64 + r) * 16 + c);
                cpa16(vlB[s2] + (r * 68 + c * 4) * 4,
                      vpLg + ((mc + 1) * 64 + r) * 16 + c);
                int dR = i >> 3, m8 = i & 7;
                cpa16(thB[s2] + (dR * 36 + m8 * 4) * 4,
                      vtHg + dR * 128 + (mc + 1) * 8 + m8);
                cpa16(tlB[s2] + (dR * 36 + m8 * 4) * 4,
                      vtLg + dR * 128 + (mc + 1) * 8 + m8);
            }
            CP_COMMIT();
            CP_WAIT1();
        } else {
            CP_WAIT0();
        }
        __syncthreads();

        // ---- scores: 16n x 32m per warp, k=128 ----
        float acc[4][4];
        #pragma unroll
        for (int j = 0; j < 4; j++)
            #pragma unroll
            for (int q = 0; q < 4; q++) acc[j][q] = 0.0f;

        const uint32_t bvh = vhB[s] + boffV, bvl = vlB[s] + boffV;
        #pragma unroll
        for (int kk = 0; kk < 8; kk++) {
            uint32_t ah0, ah1, ah2, ah3, al0, al1, al2, al3;
            ldsm_x4(ah0, ah1, ah2, ah3, aoffH + kk * 32);
            ldsm_x4(al0, al1, al2, al3, aoffL + kk * 32);
            #pragma unroll
            for (int j = 0; j < 4; j++) {
                uint32_t bh0, bh1, bl0, bl1;
                ldsm_x2(bh0, bh1, bvh + j * 2176 + kk * 32);
                ldsm_x2(bl0, bl1, bvl + j * 2176 + kk * 32);
                mma_bf16(acc[j], ah0, ah1, ah2, ah3, bh0, bh1);
                mma_bf16(acc[j], ah0, ah1, ah2, ah3, bl0, bl1);
                mma_bf16(acc[j], al0, al1, al2, al3, bh0, bh1);
            }
        }

        // ---- exp + rowsum + pack P (bf16 hi/lo) ----
        #pragma unroll
        for (int j = 0; j < 4; j++) {
            float e0 = __expf(acc[j][0] - 40.0f);
            float e1 = __expf(acc[j][1] - 40.0f);
            float e2 = __expf(acc[j][2] - 40.0f);
            float e3 = __expf(acc[j][3] - 40.0f);
            rs0 += e0 + e1;
            rs1 += e2 + e3;
            uint32_t h0 = pack_bf16x2(e1, e0);
            uint32_t l0 = pack_bf16x2(e1 - hi_f(h0), e0 - lo_f(h0));
            uint32_t h1 = pack_bf16x2(e3, e2);
            uint32_t l1 = pack_bf16x2(e3 - hi_f(h1), e2 - lo_f(h1));
            const int pc = wc * 16 + 4 * j + t;
            P32h[rA * 36 + pc] = h0;
            P32l[rA * 36 + pc] = l0;
            P32h[(rA + 8) * 36 + pc] = h1;
            P32l[(rA + 8) * 36 + pc] = l1;
        }
        __syncthreads();

        // ---- ctx: 16n x 64d per warp, k=64 ----
        const uint32_t bth = thB[s] + boffT, btl = tlB[s] + boffT;
        #pragma unroll
        for (int kk = 0; kk < 4; kk++) {
            uint32_t ph0, ph1, ph2, ph3, pl0, pl1, pl2, pl3;
            ldsm_x4(ph0, ph1, ph2, ph3, poffH + kk * 32);
            ldsm_x4(pl0, pl1, pl2, pl3, poffL + kk * 32);
            #pragma unroll
            for (int j = 0; j < 8; j++) {
                uint32_t bh0, bh1, bl0, bl1;
                ldsm_x2(bh0, bh1, bth + j * 1152 + kk * 32);
                ldsm_x2(bl0, bl1, btl + j * 1152 + kk * 32);
                mma_bf16(cacc[j], ph0, ph1, ph2, ph3, bh0, bh1);
                mma_bf16(cacc[j], pl0, pl1, pl2, pl3, bh0, bh1);
                mma_bf16(cacc[j], ph0, ph1, ph2, ph3, bl0, bl1);
            }
        }
        __syncthreads();
    }

    // ---- row sums -> inverse ----
    rs0 += __shfl_xor_sync(0xffffffffu, rs0, 1);
    rs0 += __shfl_xor_sync(0xffffffffu, rs0, 2);
    rs1 += __shfl_xor_sync(0xffffffffu, rs1, 1);
    rs1 += __shfl_xor_sync(0xffffffffu, rs1, 2);
    if (t == 0) {
        RS[wc * 64 + rA] = rs0;
        RS[wc * 64 + rA + 8] = rs1;
    }
    __syncthreads();
    if (tid < 64) INV[tid] = 1.0f / (RS[tid] + RS[64 + tid]);
    __syncthreads();

    // ---- epilogue: joint = Uc + ctx/l, write Jt, reduce over n ----
    const float iA = INV[rA], iB = INV[rA + 8];
    float* Jt = (float*)(sm + OFF_VH0);   // 64 x 132 f32 (reuses V area)
    #pragma unroll
    for (int j = 0; j < 8; j++) {
        const int d0 = 64 * wc + j * 8 + 2 * t;
        uint32_t uh = UC32h[rA * 68 + (d0 >> 1)];
        uint32_t ul = UC32l[rA * 68 + (d0 >> 1)];
        Jt[rA * 132 + d0]     = lo_f(uh) + lo_f(ul) + cacc[j][0] * iA;
        Jt[rA * 132 + d0 + 1] = hi_f(uh) + hi_f(ul) + cacc[j][1] * iA;
        uint32_t uh2 = UC32h[(rA + 8) * 68 + (d0 >> 1)];
        uint32_t ul2 = UC32l[(rA + 8) * 68 + (d0 >> 1)];
        Jt[(rA + 8) * 132 + d0]     = lo_f(uh2) + lo_f(ul2) + cacc[j][2] * iB;
        Jt[(rA + 8) * 132 + d0 + 1] = hi_f(uh2) + hi_f(ul2) + cacc[j][3] * iB;
    }
    __syncthreads();
    {
        int h = tid >> 7, d = tid & 127;
        float s = 0.0f;
        #pragma unroll
        for (int r = 0; r < 32; r++) s += Jt[(h * 32 + r) * 132 + d];
        RED[h * 128 + d] = s;
    }
    __syncthreads();
    if (tid < 128)
        part[(size_t)blockIdx.x * D_ + tid] = RED[tid] + RED[128 + tid];
}

// ============================================================================
__global__ __launch_bounds__(256)
void reduce_kernel(const float* __restrict__ part, const float* __restrict__ q,
                   float* __restrict__ out) {
    int i = blockIdx.x * blockDim.x + threadIdx.x;
    int b = i >> 7, d = i & 127;
    float s = 0.0f;
    #pragma unroll
    for (int nt = 0; nt < 8; nt++)
        s += part[(size_t)(b * 8 + nt) * D_ + d];
    out[i] = s * q[d] * (1.0f / (float)N_);
}

// ============================================================================
extern "C" void kernel_launch(void* const* d_in, const int* in_sizes, int n_in,
                              void* d_out, int out_size) {
    const float* h_c = (const float*)d_in[0];
    const float* h_p = (const float*)d_in[1];
    const float* U_w = (const float*)d_in[2];
    const float* U_b = (const float*)d_in[3];
    const float* V_w = (const float*)d_in[4];
    const float* V_b = (const float*)d_in[5];
    const float* q   = (const float*)d_in[6];
    float* out = (float*)d_out;

    void *pUcH, *pUcL, *pVpH, *pVpL, *pVtH, *pVtL, *pPart;
    cudaGetSymbolAddress(&pUcH, g_UcHi);
    cudaGetSymbolAddress(&pUcL, g_UcLo);
    cudaGetSymbolAddress(&pVpH, g_VpHi);
    cudaGetSymbolAddress(&pVpL, g_VpLo);
    cudaGetSymbolAddress(&pVtH, g_VtHi);
    cudaGetSymbolAddress(&pVtL, g_VtLo);
    cudaGetSymbolAddress(&pPart, g_part);

    const int PROJ_SMEM = (16384 + 64 * 132) * 4;
    cudaFuncSetAttribute(proj_kernel,
                         cudaFuncAttributeMaxDynamicSharedMemorySize, PROJ_SMEM);
    cudaFuncSetAttribute(attn_kernel,
                         cudaFuncAttributeMaxDynamicSharedMemorySize, ATTN_SMEM);

    proj_kernel<<<(B_ * N_) / 64, 256, PROJ_SMEM>>>(
        h_c, U_w, U_b, (__nv_bfloat16*)pUcH, (__nv_bfloat16*)pUcL);
    proj_kernel<<<(B_ * M_) / 64, 256, PROJ_SMEM>>>(
        h_p, V_w, V_b, (__nv_bfloat16*)pVpH, (__nv_bfloat16*)pVpL);
    trans_kernel<<<2048, 256>>>((const __nv_bfloat16*)pVpH,
                                (const __nv_bfloat16*)pVpL,
                                (__nv_bfloat16*)pVtH, (__nv_bfloat16*)pVtL);
    attn_kernel<<<B_ * 8, 256, ATTN_SMEM>>>((float*)pPart);
    reduce_kernel<<<(B_ * D_) / 256, 256>>>((const float*)pPart, q, out);
}

// round 8
// speedup vs baseline: 3.3870x; 1.0882x over previous
#include <cuda_runtime.h>
#include <cuda_bf16.h>
#include <cstdint>

#define B_ 64
#define N_ 512
#define M_ 1024
#define D_ 128

typedef unsigned long long ull;

extern __shared__ char dynsm[];

// ---------------- device scratch (allocation-free) ----------------
__device__ __nv_bfloat16 g_UcHi[(size_t)B_ * N_ * D_];
__device__ __nv_bfloat16 g_UcLo[(size_t)B_ * N_ * D_];
__device__ __nv_bfloat16 g_VpHi[(size_t)B_ * M_ * D_];
__device__ __nv_bfloat16 g_VpLo[(size_t)B_ * M_ * D_];
__device__ float g_part[(size_t)B_ * 8 * D_];

// ---------------- helpers ----------------
__device__ __forceinline__ ull ffma2(ull a, ull b, ull c) {
    ull d; asm("fma.rn.f32x2 %0, %1, %2, %3;" : "=l"(d) : "l"(a), "l"(b), "l"(c));
    return d;
}
__device__ __forceinline__ float2 unpack2(ull v) {
    float2 f; asm("mov.b64 {%0, %1}, %2;" : "=f"(f.x), "=f"(f.y) : "l"(v)); return f;
}
__device__ __forceinline__ uint32_t pack_bf16x2(float hi, float lo) {
    uint32_t r;
    asm("cvt.rn.bf16x2.f32 %0, %1, %2;" : "=r"(r) : "f"(hi), "f"(lo));
    return r;
}
__device__ __forceinline__ float lo_f(uint32_t p) { return __uint_as_float(p << 16); }
__device__ __forceinline__ float hi_f(uint32_t p) { return __uint_as_float(p & 0xffff0000u); }

__device__ __forceinline__ uint32_t smem_u32(const void* p) {
    uint32_t a;
    asm("{ .reg .u64 t; cvta.to.shared.u64 t, %1; cvt.u32.u64 %0, t; }"
        : "=r"(a) : "l"(p));
    return a;
}
__device__ __forceinline__ void mma_bf16(float* c, uint32_t a0, uint32_t a1,
                                         uint32_t a2, uint32_t a3,
                                         uint32_t b0, uint32_t b1) {
    asm volatile(
        "mma.sync.aligned.m16n8k16.row.col.f32.bf16.bf16.f32 "
        "{%0,%1,%2,%3},{%4,%5,%6,%7},{%8,%9},{%0,%1,%2,%3};"
        : "+f"(c[0]), "+f"(c[1]), "+f"(c[2]), "+f"(c[3])
        : "r"(a0), "r"(a1), "r"(a2), "r"(a3), "r"(b0), "r"(b1));
}
__device__ __forceinline__ void ldsm_x4(uint32_t& r0, uint32_t& r1, uint32_t& r2,
                                        uint32_t& r3, uint32_t addr) {
    asm volatile("ldmatrix.sync.aligned.m8n8.x4.shared.b16 {%0,%1,%2,%3}, [%4];"
                 : "=r"(r0), "=r"(r1), "=r"(r2), "=r"(r3) : "r"(addr));
}
__device__ __forceinline__ void ldsm_x2(uint32_t& r0, uint32_t& r1, uint32_t addr) {
    asm volatile("ldmatrix.sync.aligned.m8n8.x2.shared.b16 {%0,%1}, [%2];"
                 : "=r"(r0), "=r"(r1) : "r"(addr));
}
__device__ __forceinline__ void ldsm_x2t(uint32_t& r0, uint32_t& r1, uint32_t addr) {
    asm volatile("ldmatrix.sync.aligned.m8n8.x2.trans.shared.b16 {%0,%1}, [%2];"
                 : "=r"(r0), "=r"(r1) : "r"(addr));
}
__device__ __forceinline__ void cpa16(uint32_t dst, const void* src) {
    asm volatile("cp.async.cg.shared.global [%0], [%1], 16;"
                 :: "r"(dst), "l"(src) : "memory");
}
#define CP_COMMIT() asm volatile("cp.async.commit_group;" ::: "memory")
#define CP_WAIT1() asm volatile("cp.async.wait_group 1;" ::: "memory")
#define CP_WAIT0() asm volatile("cp.async.wait_group 0;" ::: "memory")

// ============================================================================
// Projection: relu(X @ W^T + b), fp32 FFMA2 core, bf16 hi/lo outputs
// ============================================================================
__global__ __launch_bounds__(256)
void proj_kernel(const float* __restrict__ X, const float* __restrict__ W,
                 const float* __restrict__ bias,
                 __nv_bfloat16* __restrict__ outHi,
                 __nv_bfloat16* __restrict__ outLo) {
    float* sm = (float*)dynsm;
    float* Ws = sm;
    float* Xs = sm + 16384;
    const int tid = threadIdx.x;
    const size_t row0 = (size_t)blockIdx.x * 64;

    #pragma unroll
    for (int it = 0; it < 16; it++) {
        int i = it * 1024 + tid * 4;
        int c = i >> 7, d = i & 127;
        float4 v = *(const float4*)&W[i];
        *(float4*)&Ws[c * 128 + (d ^ (((c >> 3) & 7) << 2))] = v;
    }
    #pragma unroll
    for (int it = 0; it < 8; it++) {
        int i = it * 1024 + tid * 4;
        int r = i >> 7, d = i & 127;
        *(float4*)&Xs[r * 132 + d] = *(const float4*)&X[row0 * D_ + i];
    }
    __syncthreads();

    const int cg = tid & 15, rg = tid >> 4;
    const int r0 = rg * 4, c0 = cg * 8;
    const int swz = (cg & 7) << 2;

    ull acc[4][8];
    #pragma unroll
    for (int i = 0; i < 4; i++)
        #pragma unroll
        for (int j = 0; j < 8; j++) acc[i][j] = 0ULL;

    #pragma unroll 2
    for (int d = 0; d < 128; d += 4) {
        ulonglong2 x[4];
        #pragma unroll
        for (int i = 0; i < 4; i++)
            x[i] = *(const ulonglong2*)&Xs[(r0 + i) * 132 + d];
        const int dsw = d ^ swz;
        #pragma unroll
        for (int j = 0; j < 8; j++) {
            ulonglong2 wv = *(const ulonglong2*)&Ws[(c0 + j) * 128 + dsw];
            #pragma unroll
            for (int i = 0; i < 4; i++) {
                acc[i][j] = ffma2(x[i].x, wv.x, acc[i][j]);
                acc[i][j] = ffma2(x[i].y, wv.y, acc[i][j]);
            }
        }
    }
    #pragma unroll
    for (int i = 0; i < 4; i++) {
        float o[8];
        #pragma unroll
        for (int j = 0; j < 8; j++) {
            float2 p = unpack2(acc[i][j]);
            o[j] = fmaxf(p.x + p.y + bias[c0 + j], 0.0f);
        }
        uint32_t hw[4], lw[4];
        #pragma unroll
        for (int jj = 0; jj < 4; jj++) {
            float o0 = o[2 * jj], o1 = o[2 * jj + 1];
            uint32_t h = pack_bf16x2(o1, o0);
            hw[jj] = h;
            lw[jj] = pack_bf16x2(o1 - hi_f(h), o0 - lo_f(h));
        }
        size_t go = (row0 + r0 + i) * (size_t)D_ + c0;
        *(uint4*)(outHi + go) = make_uint4(hw[0], hw[1], hw[2], hw[3]);
        *(uint4*)(outLo + go) = make_uint4(lw[0], lw[1], lw[2], lw[3]);
    }
}

// ============================================================================
// Fused attention: mma.sync bf16-split + ldmatrix(.trans) + cp.async.
// CTA = (b, 64 n-rows), 512 thr, warp grid 4(n) x 4(m/d), 16 m-chunks of 64.
// Ctx B-operand comes straight from the Vp buffers via ldmatrix.trans
// (no transposed copy anywhere).
// ============================================================================
#define OFF_UCH 0
#define OFF_UCL 17408
#define OFF_VH0 34816
#define OFF_VL0 52224
#define OFF_VH1 69632
#define OFF_VL1 87040
#define OFF_PH  104448
#define OFF_PL  113664
#define OFF_RS  122880
#define OFF_INV 123904
#define OFF_RED 124160
#define ATTN_SMEM 126208

__global__ __launch_bounds__(512, 1)
void attn_kernel(float* __restrict__ part) {
    char* sm = dynsm;
    const uint32_t smu = smem_u32(sm);
    const int tid = threadIdx.x, wid = tid >> 5, lane = tid & 31;
    const int wr = wid & 3, wc = wid >> 2;          // 4 x 4 warp grid
    const int g = lane >> 2, t = lane & 3;
    const int b = blockIdx.x >> 3, nt = blockIdx.x & 7;

    uint32_t* UC32h = (uint32_t*)(sm + OFF_UCH);   // stride 68 u32 per row
    uint32_t* UC32l = (uint32_t*)(sm + OFF_UCL);
    uint32_t* P32h  = (uint32_t*)(sm + OFF_PH);    // stride 36
    uint32_t* P32l  = (uint32_t*)(sm + OFF_PL);
    float* RS  = (float*)(sm + OFF_RS);
    float* INV = (float*)(sm + OFF_INV);
    float* RED = (float*)(sm + OFF_RED);

    const uint4* ucHg = (const uint4*)(g_UcHi + ((size_t)(b * N_ + nt * 64)) * D_);
    const uint4* ucLg = (const uint4*)(g_UcLo + ((size_t)(b * N_ + nt * 64)) * D_);
    const uint4* vpHg = (const uint4*)(g_VpHi + (size_t)b * M_ * D_);
    const uint4* vpLg = (const uint4*)(g_VpLo + (size_t)b * M_ * D_);

    // stage Uc (64 rows x 16 uint4 per buffer)
    uint4* UH4 = (uint4*)(sm + OFF_UCH);
    uint4* UL4 = (uint4*)(sm + OFF_UCL);
    #pragma unroll
    for (int it = 0; it < 2; it++) {
        int i = it * 512 + tid;
        int r = i >> 4, c = i & 15;
        UH4[r * 17 + c] = ucHg[i];
        UL4[r * 17 + c] = ucLg[i];
    }

    const uint32_t vhB[2] = {smu + OFF_VH0, smu + OFF_VH1};
    const uint32_t vlB[2] = {smu + OFF_VL0, smu + OFF_VL1};

    // per-lane ldmatrix address components
    const int l7 = lane & 7, l8 = (lane >> 3) & 1, l16 = lane >> 4;
    // A (scores/Uc): rows 16wr..+16, x4
    const uint32_t aoffH = smu + OFF_UCH + ((16 * wr + l7 + l8 * 8) * 68 + l16 * 4) * 4;
    const uint32_t aoffL = smu + OFF_UCL + ((16 * wr + l7 + l8 * 8) * 68 + l16 * 4) * 4;
    // B (scores/V): n-rows = m-tile (wc*16 + j*8), x2 non-trans
    const uint32_t boffV = ((wc * 16 + l7) * 68 + l8 * 4) * 4;
    // A (ctx/P): rows 16wr..+16, x4, stride 36
    const uint32_t poffH = smu + OFF_PH + ((16 * wr + l7 + l8 * 8) * 36 + l16 * 4) * 4;
    const uint32_t poffL = smu + OFF_PL + ((16 * wr + l7 + l8 * 8) * 36 + l16 * 4) * 4;
    // B (ctx): trans load from Vp buffer: rows = m (k-dim), word col = d-tile
    // d-tile for warp = wc*32 + j*8  -> word col = wc*16 + j*4
    const uint32_t boffT = ((l8 * 8 + l7) * 68 + wc * 16) * 4;

    const int rA = 16 * wr + g;
    float cacc[4][4];
    #pragma unroll
    for (int j = 0; j < 4; j++)
        #pragma unroll
        for (int q = 0; q < 4; q++) cacc[j][q] = 0.0f;
    float rs0 = 0.0f, rs1 = 0.0f;

    // stage chunk 0 (V only: 64 rows x 16 uint4 x2 bufs = 2048 cpa16)
    #pragma unroll
    for (int it = 0; it < 2; it++) {
        int i = it * 512 + tid;
        int r = i >> 4, c = i & 15;
        cpa16(vhB[0] + (r * 68 + c * 4) * 4, vpHg + r * 16 + c);
        cpa16(vlB[0] + (r * 68 + c * 4) * 4, vpLg + r * 16 + c);
    }
    CP_COMMIT();

    for (int mc = 0; mc < 16; mc++) {
        const int s = mc & 1;
        if (mc + 1 < 16) {
            const int s2 = (mc + 1) & 1;
            #pragma unroll
            for (int it = 0; it < 2; it++) {
                int i = it * 512 + tid;
                int r = i >> 4, c = i & 15;
                cpa16(vhB[s2] + (r * 68 + c * 4) * 4,
                      vpHg + ((mc + 1) * 64 + r) * 16 + c);
                cpa16(vlB[s2] + (r * 68 + c * 4) * 4,
                      vpLg + ((mc + 1) * 64 + r) * 16 + c);
            }
            CP_COMMIT();
            CP_WAIT1();
        } else {
            CP_WAIT0();
        }
        __syncthreads();

        // ---- scores: 16n x 16m per warp, k=128, 2 acc chains per j ----
        float accA[2][4], accB[2][4];
        #pragma unroll
        for (int j = 0; j < 2; j++)
            #pragma unroll
            for (int q = 0; q < 4; q++) { accA[j][q] = 0.0f; accB[j][q] = 0.0f; }

        const uint32_t bvh = vhB[s] + boffV, bvl = vlB[s] + boffV;
        #pragma unroll
        for (int kk = 0; kk < 8; kk++) {
            uint32_t ah0, ah1, ah2, ah3, al0, al1, al2, al3;
            ldsm_x4(ah0, ah1, ah2, ah3, aoffH + kk * 32);
            ldsm_x4(al0, al1, al2, al3, aoffL + kk * 32);
            #pragma unroll
            for (int j = 0; j < 2; j++) {
                uint32_t bh0, bh1, bl0, bl1;
                ldsm_x2(bh0, bh1, bvh + j * 2176 + kk * 32);
                ldsm_x2(bl0, bl1, bvl + j * 2176 + kk * 32);
                mma_bf16(accA[j], ah0, ah1, ah2, ah3, bh0, bh1);
                mma_bf16(accB[j], ah0, ah1, ah2, ah3, bl0, bl1);
                mma_bf16(accB[j], al0, al1, al2, al3, bh0, bh1);
            }
        }

        // ---- exp + rowsum + pack P (bf16 hi/lo) ----
        #pragma unroll
        for (int j = 0; j < 2; j++) {
            float e0 = __expf(accA[j][0] + accB[j][0] - 40.0f);
            float e1 = __expf(accA[j][1] + accB[j][1] - 40.0f);
            float e2 = __expf(accA[j][2] + accB[j][2] - 40.0f);
            float e3 = __expf(accA[j][3] + accB[j][3] - 40.0f);
            rs0 += e0 + e1;
            rs1 += e2 + e3;
            uint32_t h0 = pack_bf16x2(e1, e0);
            uint32_t l0 = pack_bf16x2(e1 - hi_f(h0), e0 - lo_f(h0));
            uint32_t h1 = pack_bf16x2(e3, e2);
            uint32_t l1 = pack_bf16x2(e3 - hi_f(h1), e2 - lo_f(h1));
            const int pc = wc * 8 + 4 * j + t;
            P32h[rA * 36 + pc] = h0;
            P32l[rA * 36 + pc] = l0;
            P32h[(rA + 8) * 36 + pc] = h1;
            P32l[(rA + 8) * 36 + pc] = l1;
        }
        __syncthreads();

        // ---- ctx: 16n x 32d per warp, k=64, B via ldmatrix.trans on Vp ----
        const uint32_t bth = vhB[s] + boffT, btl = vlB[s] + boffT;
        #pragma unroll
        for (int kk = 0; kk < 4; kk++) {
            uint32_t ph0, ph1, ph2, ph3, pl0, pl1, pl2, pl3;
            ldsm_x4(ph0, ph1, ph2, ph3, poffH + kk * 32);
            ldsm_x4(pl0, pl1, pl2, pl3, poffL + kk * 32);
            #pragma unroll
            for (int j = 0; j < 4; j++) {
                uint32_t bh0, bh1, bl0, bl1;
                ldsm_x2t(bh0, bh1, bth + kk * 4352 + j * 16);
                ldsm_x2t(bl0, bl1, btl + kk * 4352 + j * 16);
                mma_bf16(cacc[j], ph0, ph1, ph2, ph3, bh0, bh1);
                mma_bf16(cacc[j], pl0, pl1, pl2, pl3, bh0, bh1);
                mma_bf16(cacc[j], ph0, ph1, ph2, ph3, bl0, bl1);
            }
        }
        __syncthreads();
    }

    // ---- row sums -> inverse (4 wc slices per row) ----
    rs0 += __shfl_xor_sync(0xffffffffu, rs0, 1);
    rs0 += __shfl_xor_sync(0xffffffffu, rs0, 2);
    rs1 += __shfl_xor_sync(0xffffffffu, rs1, 1);
    rs1 += __shfl_xor_sync(0xffffffffu, rs1, 2);
    if (t == 0) {
        RS[wc * 64 + rA] = rs0;
        RS[wc * 64 + rA + 8] = rs1;
    }
    __syncthreads();
    if (tid < 64)
        INV[tid] = 1.0f / (RS[tid] + RS[64 + tid] + RS[128 + tid] + RS[192 + tid]);
    __syncthreads();

    // ---- epilogue: joint = Uc + ctx/l, write Jt, reduce over n ----
    const float iA = INV[rA], iB = INV[rA + 8];
    float* Jt = (float*)(sm + OFF_VH0);   // 64 x 132 f32 (reuses V area, 33.8KB)
    #pragma unroll
    for (int j = 0; j < 4; j++) {
        const int d0 = 32 * wc + j * 8 + 2 * t;
        uint32_t uh = UC32h[rA * 68 + (d0 >> 1)];
        uint32_t ul = UC32l[rA * 68 + (d0 >> 1)];
        Jt[rA * 132 + d0]     = lo_f(uh) + lo_f(ul) + cacc[j][0] * iA;
        Jt[rA * 132 + d0 + 1] = hi_f(uh) + hi_f(ul) + cacc[j][1] * iA;
        uint32_t uh2 = UC32h[(rA + 8) * 68 + (d0 >> 1)];
        uint32_t ul2 = UC32l[(rA + 8) * 68 + (d0 >> 1)];
        Jt[(rA + 8) * 132 + d0]     = lo_f(uh2) + lo_f(ul2) + cacc[j][2] * iB;
        Jt[(rA + 8) * 132 + d0 + 1] = hi_f(uh2) + hi_f(ul2) + cacc[j][3] * iB;
    }
    __syncthreads();
    {
        int h = tid >> 7, d = tid & 127;   // 4 groups x 16 rows
        float s = 0.0f;
        #pragma unroll
        for (int r = 0; r < 16; r++) s += Jt[(h * 16 + r) * 132 + d];
        RED[h * 128 + d] = s;
    }
    __syncthreads();
    if (tid < 128)
        part[(size_t)blockIdx.x * D_ + tid] =
            RED[tid] + RED[128 + tid] + RED[256 + tid] + RED[384 + tid];
}

// ============================================================================
__global__ __launch_bounds__(256)
void reduce_kernel(const float* __restrict__ part, const float* __restrict__ q,
                   float* __restrict__ out) {
    int i = blockIdx.x * blockDim.x + threadIdx.x;
    int b = i >> 7, d = i & 127;
    float s = 0.0f;
    #pragma unroll
    for (int nt = 0; nt < 8; nt++)
        s += part[(size_t)(b * 8 + nt) * D_ + d];
    out[i] = s * q[d] * (1.0f / (float)N_);
}

// ============================================================================
extern "C" void kernel_launch(void* const* d_in, const int* in_sizes, int n_in,
                              void* d_out, int out_size) {
    const float* h_c = (const float*)d_in[0];
    const float* h_p = (const float*)d_in[1];
    const float* U_w = (const float*)d_in[2];
    const float* U_b = (const float*)d_in[3];
    const float* V_w = (const float*)d_in[4];
    const float* V_b = (const float*)d_in[5];
    const float* q   = (const float*)d_in[6];
    float* out = (float*)d_out;

    void *pUcH, *pUcL, *pVpH, *pVpL, *pPart;
    cudaGetSymbolAddress(&pUcH, g_UcHi);
    cudaGetSymbolAddress(&pUcL, g_UcLo);
    cudaGetSymbolAddress(&pVpH, g_VpHi);
    cudaGetSymbolAddress(&pVpL, g_VpLo);
    cudaGetSymbolAddress(&pPart, g_part);

    const int PROJ_SMEM = (16384 + 64 * 132) * 4;
    cudaFuncSetAttribute(proj_kernel,
                         cudaFuncAttributeMaxDynamicSharedMemorySize, PROJ_SMEM);
    cudaFuncSetAttribute(attn_kernel,
                         cudaFuncAttributeMaxDynamicSharedMemorySize, ATTN_SMEM);

    proj_kernel<<<(B_ * N_) / 64, 256, PROJ_SMEM>>>(
        h_c, U_w, U_b, (__nv_bfloat16*)pUcH, (__nv_bfloat16*)pUcL);
    proj_kernel<<<(B_ * M_) / 64, 256, PROJ_SMEM>>>(
        h_p, V_w, V_b, (__nv_bfloat16*)pVpH, (__nv_bfloat16*)pVpL);
    attn_kernel<<<B_ * 8, 512, ATTN_SMEM>>>((float*)pPart);
    reduce_kernel<<<(B_ * D_) / 256, 256>>>((const float*)pPart, q, out);
}

// round 9
// speedup vs baseline: 3.9800x; 1.1751x over previous
#include <cuda_runtime.h>
#include <cuda_bf16.h>
#include <cstdint>

#define B_ 64
#define N_ 512
#define M_ 1024
#define D_ 128

typedef unsigned long long ull;

extern __shared__ char dynsm[];

// ---------------- device scratch (allocation-free) ----------------
__device__ __nv_bfloat16 g_UcHi[(size_t)B_ * N_ * D_];
__device__ __nv_bfloat16 g_UcLo[(size_t)B_ * N_ * D_];
__device__ __nv_bfloat16 g_VpHi[(size_t)B_ * M_ * D_];
__device__ __nv_bfloat16 g_VpLo[(size_t)B_ * M_ * D_];
__device__ float g_part[(size_t)B_ * 8 * D_];

// ---------------- helpers ----------------
__device__ __forceinline__ uint32_t pack_bf16x2(float hi, float lo) {
    uint32_t r;
    asm("cvt.rn.bf16x2.f32 %0, %1, %2;" : "=r"(r) : "f"(hi), "f"(lo));
    return r;
}
__device__ __forceinline__ float lo_f(uint32_t p) { return __uint_as_float(p << 16); }
__device__ __forceinline__ float hi_f(uint32_t p) { return __uint_as_float(p & 0xffff0000u); }

__device__ __forceinline__ uint32_t smem_u32(const void* p) {
    uint32_t a;
    asm("{ .reg .u64 t; cvta.to.shared.u64 t, %1; cvt.u32.u64 %0, t; }"
        : "=r"(a) : "l"(p));
    return a;
}
__device__ __forceinline__ void mma_bf16(float* c, uint32_t a0, uint32_t a1,
                                         uint32_t a2, uint32_t a3,
                                         uint32_t b0, uint32_t b1) {
    asm volatile(
        "mma.sync.aligned.m16n8k16.row.col.f32.bf16.bf16.f32 "
        "{%0,%1,%2,%3},{%4,%5,%6,%7},{%8,%9},{%0,%1,%2,%3};"
        : "+f"(c[0]), "+f"(c[1]), "+f"(c[2]), "+f"(c[3])
        : "r"(a0), "r"(a1), "r"(a2), "r"(a3), "r"(b0), "r"(b1));
}
__device__ __forceinline__ void ldsm_x4(uint32_t& r0, uint32_t& r1, uint32_t& r2,
                                        uint32_t& r3, uint32_t addr) {
    asm volatile("ldmatrix.sync.aligned.m8n8.x4.shared.b16 {%0,%1,%2,%3}, [%4];"
                 : "=r"(r0), "=r"(r1), "=r"(r2), "=r"(r3) : "r"(addr));
}
__device__ __forceinline__ void ldsm_x2(uint32_t& r0, uint32_t& r1, uint32_t addr) {
    asm volatile("ldmatrix.sync.aligned.m8n8.x2.shared.b16 {%0,%1}, [%2];"
                 : "=r"(r0), "=r"(r1) : "r"(addr));
}
__device__ __forceinline__ void ldsm_x2t(uint32_t& r0, uint32_t& r1, uint32_t addr) {
    asm volatile("ldmatrix.sync.aligned.m8n8.x2.trans.shared.b16 {%0,%1}, [%2];"
                 : "=r"(r0), "=r"(r1) : "r"(addr));
}
__device__ __forceinline__ void cpa16(uint32_t dst, const void* src) {
    asm volatile("cp.async.cg.shared.global [%0], [%1], 16;"
                 :: "r"(dst), "l"(src) : "memory");
}
#define CP_COMMIT() asm volatile("cp.async.commit_group;" ::: "memory")
#define CP_WAIT0() asm volatile("cp.async.wait_group 0;" ::: "memory")

// ============================================================================
// Projection via HMMA: relu(X @ W^T + b) -> bf16 hi/lo.
// CTA = 64 rows x 128 cols, 512 thr, warp grid 4(rows) x 4(cols).
// 3-term bf16-split, fp32 accumulate; X/W converted to hi/lo in smem.
// ============================================================================
#define PJ_WH 0
#define PJ_WL 34816
#define PJ_XH 69632
#define PJ_XL 87040
#define PROJ_SMEM 104448

__global__ __launch_bounds__(512, 1)
void proj_kernel(const float* __restrict__ X, const float* __restrict__ W,
                 const float* __restrict__ bias,
                 __nv_bfloat16* __restrict__ outHi,
                 __nv_bfloat16* __restrict__ outLo) {
    char* sm = dynsm;
    const uint32_t smu = smem_u32(sm);
    const int tid = threadIdx.x, wid = tid >> 5, lane = tid & 31;
    const int wr = wid & 3, wc = wid >> 2;
    const int g = lane >> 2, t = lane & 3;
    const size_t row0 = (size_t)blockIdx.x * 64;

    uint32_t* WH = (uint32_t*)(sm + PJ_WH);
    uint32_t* WL = (uint32_t*)(sm + PJ_WL);
    uint32_t* XH = (uint32_t*)(sm + PJ_XH);
    uint32_t* XL = (uint32_t*)(sm + PJ_XL);

    // stage W (128x128 fp32 -> hi/lo bf16), rows stride 68 u32
    const float4* Wg = (const float4*)W;
    #pragma unroll
    for (int it = 0; it < 8; it++) {
        int i = it * 512 + tid;           // 4096 float4
        int r = i >> 5, c4 = i & 31;
        float4 v = Wg[i];
        uint32_t h0 = pack_bf16x2(v.y, v.x);
        uint32_t l0 = pack_bf16x2(v.y - hi_f(h0), v.x - lo_f(h0));
        uint32_t h1 = pack_bf16x2(v.w, v.z);
        uint32_t l1 = pack_bf16x2(v.w - hi_f(h1), v.z - lo_f(h1));
        WH[r * 68 + c4 * 2] = h0; WH[r * 68 + c4 * 2 + 1] = h1;
        WL[r * 68 + c4 * 2] = l0; WL[r * 68 + c4 * 2 + 1] = l1;
    }
    // stage X tile (64x128)
    const float4* Xg = (const float4*)(X + row0 * D_);
    #pragma unroll
    for (int it = 0; it < 4; it++) {
        int i = it * 512 + tid;           // 2048 float4
        int r = i >> 5, c4 = i & 31;
        float4 v = Xg[i];
        uint32_t h0 = pack_bf16x2(v.y, v.x);
        uint32_t l0 = pack_bf16x2(v.y - hi_f(h0), v.x - lo_f(h0));
        uint32_t h1 = pack_bf16x2(v.w, v.z);
        uint32_t l1 = pack_bf16x2(v.w - hi_f(h1), v.z - lo_f(h1));
        XH[r * 68 + c4 * 2] = h0; XH[r * 68 + c4 * 2 + 1] = h1;
        XL[r * 68 + c4 * 2] = l0; XL[r * 68 + c4 * 2 + 1] = l1;
    }
    __syncthreads();

    const int l7 = lane & 7, l8 = (lane >> 3) & 1, l16 = lane >> 4;
    const uint32_t aoffH = smu + PJ_XH + ((16 * wr + l7 + l8 * 8) * 68 + l16 * 4) * 4;
    const uint32_t aoffL = smu + PJ_XL + ((16 * wr + l7 + l8 * 8) * 68 + l16 * 4) * 4;
    const uint32_t boffH = smu + PJ_WH + ((wc * 32 + l7) * 68 + l8 * 4) * 4;
    const uint32_t boffL = smu + PJ_WL + ((wc * 32 + l7) * 68 + l8 * 4) * 4;

    float accA[4][4], accB[4][4];
    #pragma unroll
    for (int j = 0; j < 4; j++)
        #pragma unroll
        for (int q = 0; q < 4; q++) { accA[j][q] = 0.0f; accB[j][q] = 0.0f; }

    #pragma unroll
    for (int kk = 0; kk < 8; kk++) {
        uint32_t ah0, ah1, ah2, ah3, al0, al1, al2, al3;
        ldsm_x4(ah0, ah1, ah2, ah3, aoffH + kk * 32);
        ldsm_x4(al0, al1, al2, al3, aoffL + kk * 32);
        #pragma unroll
        for (int j = 0; j < 4; j++) {
            uint32_t bh0, bh1, bl0, bl1;
            ldsm_x2(bh0, bh1, boffH + j * 2176 + kk * 32);
            ldsm_x2(bl0, bl1, boffL + j * 2176 + kk * 32);
            mma_bf16(accA[j], ah0, ah1, ah2, ah3, bh0, bh1);
            mma_bf16(accB[j], ah0, ah1, ah2, ah3, bl0, bl1);
            mma_bf16(accB[j], al0, al1, al2, al3, bh0, bh1);
        }
    }

    // epilogue: bias + relu + hi/lo split, direct u32 stores
    const int rA = 16 * wr + g;
    const float2* b2 = (const float2*)bias;
    uint32_t* oH = (uint32_t*)outHi;
    uint32_t* oL = (uint32_t*)outLo;
    #pragma unroll
    for (int j = 0; j < 4; j++) {
        const int cpair = wc * 16 + j * 4 + t;    // u32 col (bf16 cols 2c, 2c+1)
        float2 bb = b2[cpair];
        float o0 = fmaxf(accA[j][0] + accB[j][0] + bb.x, 0.0f);
        float o1 = fmaxf(accA[j][1] + accB[j][1] + bb.y, 0.0f);
        uint32_t h = pack_bf16x2(o1, o0);
        uint32_t l = pack_bf16x2(o1 - hi_f(h), o0 - lo_f(h));
        oH[(row0 + rA) * 64 + cpair] = h;
        oL[(row0 + rA) * 64 + cpair] = l;
        float o2 = fmaxf(accA[j][2] + accB[j][2] + bb.x, 0.0f);
        float o3 = fmaxf(accA[j][3] + accB[j][3] + bb.y, 0.0f);
        uint32_t h2 = pack_bf16x2(o3, o2);
        uint32_t l2 = pack_bf16x2(o3 - hi_f(h2), o2 - lo_f(h2));
        oH[(row0 + rA + 8) * 64 + cpair] = h2;
        oL[(row0 + rA + 8) * 64 + cpair] = l2;
    }
}

// ============================================================================
// Fused attention: mma.sync bf16-split + ldmatrix(.trans) + cp.async.
// CTA = (b, 64 n-rows), 512 thr, warp grid 4(n) x 4(m/d), 16 m-chunks of 64.
// 2 barriers per chunk (prefetch issued after the top barrier).
// ============================================================================
#define OFF_UCH 0
#define OFF_UCL 17408
#define OFF_VH0 34816
#define OFF_VL0 52224
#define OFF_VH1 69632
#define OFF_VL1 87040
#define OFF_PH  104448
#define OFF_PL  113664
#define OFF_RS  122880
#define OFF_INV 123904
#define OFF_RED 124160
#define ATTN_SMEM 126208

__global__ __launch_bounds__(512, 1)
void attn_kernel(float* __restrict__ part) {
    char* sm = dynsm;
    const uint32_t smu = smem_u32(sm);
    const int tid = threadIdx.x, wid = tid >> 5, lane = tid & 31;
    const int wr = wid & 3, wc = wid >> 2;          // 4 x 4 warp grid
    const int g = lane >> 2, t = lane & 3;
    const int b = blockIdx.x >> 3, nt = blockIdx.x & 7;

    uint32_t* UC32h = (uint32_t*)(sm + OFF_UCH);   // stride 68 u32 per row
    uint32_t* UC32l = (uint32_t*)(sm + OFF_UCL);
    uint32_t* P32h  = (uint32_t*)(sm + OFF_PH);    // stride 36
    uint32_t* P32l  = (uint32_t*)(sm + OFF_PL);
    float* RS  = (float*)(sm + OFF_RS);
    float* INV = (float*)(sm + OFF_INV);
    float* RED = (float*)(sm + OFF_RED);

    const uint4* ucHg = (const uint4*)(g_UcHi + ((size_t)(b * N_ + nt * 64)) * D_);
    const uint4* ucLg = (const uint4*)(g_UcLo + ((size_t)(b * N_ + nt * 64)) * D_);
    const uint4* vpHg = (const uint4*)(g_VpHi + (size_t)b * M_ * D_);
    const uint4* vpLg = (const uint4*)(g_VpLo + (size_t)b * M_ * D_);

    // stage Uc (64 rows x 16 uint4 per buffer)
    uint4* UH4 = (uint4*)(sm + OFF_UCH);
    uint4* UL4 = (uint4*)(sm + OFF_UCL);
    #pragma unroll
    for (int it = 0; it < 2; it++) {
        int i = it * 512 + tid;
        int r = i >> 4, c = i & 15;
        UH4[r * 17 + c] = ucHg[i];
        UL4[r * 17 + c] = ucLg[i];
    }

    const uint32_t vhB[2] = {smu + OFF_VH0, smu + OFF_VH1};
    const uint32_t vlB[2] = {smu + OFF_VL0, smu + OFF_VL1};

    const int l7 = lane & 7, l8 = (lane >> 3) & 1, l16 = lane >> 4;
    const uint32_t aoffH = smu + OFF_UCH + ((16 * wr + l7 + l8 * 8) * 68 + l16 * 4) * 4;
    const uint32_t aoffL = smu + OFF_UCL + ((16 * wr + l7 + l8 * 8) * 68 + l16 * 4) * 4;
    const uint32_t boffV = ((wc * 16 + l7) * 68 + l8 * 4) * 4;
    const uint32_t poffH = smu + OFF_PH + ((16 * wr + l7 + l8 * 8) * 36 + l16 * 4) * 4;
    const uint32_t poffL = smu + OFF_PL + ((16 * wr + l7 + l8 * 8) * 36 + l16 * 4) * 4;
    const uint32_t boffT = ((l8 * 8 + l7) * 68 + wc * 16) * 4;

    const int rA = 16 * wr + g;
    float cacc[4][4];
    #pragma unroll
    for (int j = 0; j < 4; j++)
        #pragma unroll
        for (int q = 0; q < 4; q++) cacc[j][q] = 0.0f;
    float rs0 = 0.0f, rs1 = 0.0f;

    // stage chunk 0
    #pragma unroll
    for (int it = 0; it < 2; it++) {
        int i = it * 512 + tid;
        int r = i >> 4, c = i & 15;
        cpa16(vhB[0] + (r * 68 + c * 4) * 4, vpHg + r * 16 + c);
        cpa16(vlB[0] + (r * 68 + c * 4) * 4, vpLg + r * 16 + c);
    }
    CP_COMMIT();

    for (int mc = 0; mc < 16; mc++) {
        const int s = mc & 1;
        CP_WAIT0();
        __syncthreads();
        // prefetch chunk mc+1 (safe: all warps finished ctx(mc-1) reading s^1)
        if (mc + 1 < 16) {
            const int s2 = s ^ 1;
            #pragma unroll
            for (int it = 0; it < 2; it++) {
                int i = it * 512 + tid;
                int r = i >> 4, c = i & 15;
                cpa16(vhB[s2] + (r * 68 + c * 4) * 4,
                      vpHg + ((mc + 1) * 64 + r) * 16 + c);
                cpa16(vlB[s2] + (r * 68 + c * 4) * 4,
                      vpLg + ((mc + 1) * 64 + r) * 16 + c);
            }
            CP_COMMIT();
        }

        // ---- scores: 16n x 16m per warp, k=128, 2 acc chains per j ----
        float accA[2][4], accB[2][4];
        #pragma unroll
        for (int j = 0; j < 2; j++)
            #pragma unroll
            for (int q = 0; q < 4; q++) { accA[j][q] = 0.0f; accB[j][q] = 0.0f; }

        const uint32_t bvh = vhB[s] + boffV, bvl = vlB[s] + boffV;
        #pragma unroll
        for (int kk = 0; kk < 8; kk++) {
            uint32_t ah0, ah1, ah2, ah3, al0, al1, al2, al3;
            ldsm_x4(ah0, ah1, ah2, ah3, aoffH + kk * 32);
            ldsm_x4(al0, al1, al2, al3, aoffL + kk * 32);
            #pragma unroll
            for (int j = 0; j < 2; j++) {
                uint32_t bh0, bh1, bl0, bl1;
                ldsm_x2(bh0, bh1, bvh + j * 2176 + kk * 32);
                ldsm_x2(bl0, bl1, bvl + j * 2176 + kk * 32);
                mma_bf16(accA[j], ah0, ah1, ah2, ah3, bh0, bh1);
                mma_bf16(accB[j], ah0, ah1, ah2, ah3, bl0, bl1);
                mma_bf16(accB[j], al0, al1, al2, al3, bh0, bh1);
            }
        }

        // ---- exp + rowsum + pack P (bf16 hi/lo) ----
        #pragma unroll
        for (int j = 0; j < 2; j++) {
            float e0 = __expf(accA[j][0] + accB[j][0] - 40.0f);
            float e1 = __expf(accA[j][1] + accB[j][1] - 40.0f);
            float e2 = __expf(accA[j][2] + accB[j][2] - 40.0f);
            float e3 = __expf(accA[j][3] + accB[j][3] - 40.0f);
            rs0 += e0 + e1;
            rs1 += e2 + e3;
            uint32_t h0 = pack_bf16x2(e1, e0);
            uint32_t l0 = pack_bf16x2(e1 - hi_f(h0), e0 - lo_f(h0));
            uint32_t h1 = pack_bf16x2(e3, e2);
            uint32_t l1 = pack_bf16x2(e3 - hi_f(h1), e2 - lo_f(h1));
            const int pc = wc * 8 + 4 * j + t;
            P32h[rA * 36 + pc] = h0;
            P32l[rA * 36 + pc] = l0;
            P32h[(rA + 8) * 36 + pc] = h1;
            P32l[(rA + 8) * 36 + pc] = l1;
        }
        __syncthreads();

        // ---- ctx: 16n x 32d per warp, k=64, B via ldmatrix.trans on Vp ----
        const uint32_t bth = vhB[s] + boffT, btl = vlB[s] + boffT;
        #pragma unroll
        for (int kk = 0; kk < 4; kk++) {
            uint32_t ph0, ph1, ph2, ph3, pl0, pl1, pl2, pl3;
            ldsm_x4(ph0, ph1, ph2, ph3, poffH + kk * 32);
            ldsm_x4(pl0, pl1, pl2, pl3, poffL + kk * 32);
            #pragma unroll
            for (int j = 0; j < 4; j++) {
                uint32_t bh0, bh1, bl0, bl1;
                ldsm_x2t(bh0, bh1, bth + kk * 4352 + j * 16);
                ldsm_x2t(bl0, bl1, btl + kk * 4352 + j * 16);
                mma_bf16(cacc[j], ph0, ph1, ph2, ph3, bh0, bh1);
                mma_bf16(cacc[j], pl0, pl1, pl2, pl3, bh0, bh1);
                mma_bf16(cacc[j], ph0, ph1, ph2, ph3, bl0, bl1);
            }
        }
        // no end-of-loop barrier: top barrier of next chunk provides ordering
    }

    // ---- row sums -> inverse (4 wc slices per row) ----
    rs0 += __shfl_xor_sync(0xffffffffu, rs0, 1);
    rs0 += __shfl_xor_sync(0xffffffffu, rs0, 2);
    rs1 += __shfl_xor_sync(0xffffffffu, rs1, 1);
    rs1 += __shfl_xor_sync(0xffffffffu, rs1, 2);
    if (t == 0) {
        RS[wc * 64 + rA] = rs0;
        RS[wc * 64 + rA + 8] = rs1;
    }
    __syncthreads();
    if (tid < 64)
        INV[tid] = 1.0f / (RS[tid] + RS[64 + tid] + RS[128 + tid] + RS[192 + tid]);
    __syncthreads();

    // ---- epilogue: joint = Uc + ctx/l, write Jt, reduce over n ----
    const float iA = INV[rA], iB = INV[rA + 8];
    float* Jt = (float*)(sm + OFF_VH0);   // 64 x 132 f32 (reuses V area)
    #pragma unroll
    for (int j = 0; j < 4; j++) {
        const int d0 = 32 * wc + j * 8 + 2 * t;
        uint32_t uh = UC32h[rA * 68 + (d0 >> 1)];
        uint32_t ul = UC32l[rA * 68 + (d0 >> 1)];
        Jt[rA * 132 + d0]     = lo_f(uh) + lo_f(ul) + cacc[j][0] * iA;
        Jt[rA * 132 + d0 + 1] = hi_f(uh) + hi_f(ul) + cacc[j][1] * iA;
        uint32_t uh2 = UC32h[(rA + 8) * 68 + (d0 >> 1)];
        uint32_t ul2 = UC32l[(rA + 8) * 68 + (d0 >> 1)];
        Jt[(rA + 8) * 132 + d0]     = lo_f(uh2) + lo_f(ul2) + cacc[j][2] * iB;
        Jt[(rA + 8) * 132 + d0 + 1] = hi_f(uh2) + hi_f(ul2) + cacc[j][3] * iB;
    }
    __syncthreads();
    {
        int h = tid >> 7, d = tid & 127;   // 4 groups x 16 rows
        float s = 0.0f;
        #pragma unroll
        for (int r = 0; r < 16; r++) s += Jt[(h * 16 + r) * 132 + d];
        RED[h * 128 + d] = s;
    }
    __syncthreads();
    if (tid < 128)
        part[(size_t)blockIdx.x * D_ + tid] =
            RED[tid] + RED[128 + tid] + RED[256 + tid] + RED[384 + tid];
}

// ============================================================================
__global__ __launch_bounds__(256)
void reduce_kernel(const float* __restrict__ part, const float* __restrict__ q,
                   float* __restrict__ out) {
    int i = blockIdx.x * blockDim.x + threadIdx.x;
    int b = i >> 7, d = i & 127;
    float s = 0.0f;
    #pragma unroll
    for (int nt = 0; nt < 8; nt++)
        s += part[(size_t)(b * 8 + nt) * D_ + d];
    out[i] = s * q[d] * (1.0f / (float)N_);
}

// ============================================================================
extern "C" void kernel_launch(void* const* d_in, const int* in_sizes, int n_in,
                              void* d_out, int out_size) {
    const float* h_c = (const float*)d_in[0];
    const float* h_p = (const float*)d_in[1];
    const float* U_w = (const float*)d_in[2];
    const float* U_b = (const float*)d_in[3];
    const float* V_w = (const float*)d_in[4];
    const float* V_b = (const float*)d_in[5];
    const float* q   = (const float*)d_in[6];
    float* out = (float*)d_out;

    void *pUcH, *pUcL, *pVpH, *pVpL, *pPart;
    cudaGetSymbolAddress(&pUcH, g_UcHi);
    cudaGetSymbolAddress(&pUcL, g_UcLo);
    cudaGetSymbolAddress(&pVpH, g_VpHi);
    cudaGetSymbolAddress(&pVpL, g_VpLo);
    cudaGetSymbolAddress(&pPart, g_part);

    cudaFuncSetAttribute(proj_kernel,
                         cudaFuncAttributeMaxDynamicSharedMemorySize, PROJ_SMEM);
    cudaFuncSetAttribute(attn_kernel,
                         cudaFuncAttributeMaxDynamicSharedMemorySize, ATTN_SMEM);

    proj_kernel<<<(B_ * N_) / 64, 512, PROJ_SMEM>>>(
        h_c, U_w, U_b, (__nv_bfloat16*)pUcH, (__nv_bfloat16*)pUcL);
    proj_kernel<<<(B_ * M_) / 64, 512, PROJ_SMEM>>>(
        h_p, V_w, V_b, (__nv_bfloat16*)pVpH, (__nv_bfloat16*)pVpL);
    attn_kernel<<<B_ * 8, 512, ATTN_SMEM>>>((float*)pPart);
    reduce_kernel<<<(B_ * D_) / 256, 256>>>((const float*)pPart, q, out);
}

// round 11
// speedup vs baseline: 4.1274x; 1.0370x over previous
#include <cuda_runtime.h>
#include <cuda_bf16.h>
#include <cstdint>

#define B_ 64
#define N_ 512
#define M_ 1024
#define D_ 128

typedef unsigned long long ull;

extern __shared__ char dynsm[];

// ---------------- device scratch (allocation-free) ----------------
__device__ __nv_bfloat16 g_UcHi[(size_t)B_ * N_ * D_];
__device__ __nv_bfloat16 g_UcLo[(size_t)B_ * N_ * D_];
__device__ __nv_bfloat16 g_VpHi[(size_t)B_ * M_ * D_];
__device__ __nv_bfloat16 g_VpLo[(size_t)B_ * M_ * D_];
__device__ float g_part[(size_t)B_ * 8 * D_];

// ---------------- helpers ----------------
__device__ __forceinline__ uint32_t pack_bf16x2(float hi, float lo) {
    uint32_t r;
    asm("cvt.rn.bf16x2.f32 %0, %1, %2;" : "=r"(r) : "f"(hi), "f"(lo));
    return r;
}
__device__ __forceinline__ float lo_f(uint32_t p) { return __uint_as_float(p << 16); }
__device__ __forceinline__ float hi_f(uint32_t p) { return __uint_as_float(p & 0xffff0000u); }

__device__ __forceinline__ uint32_t smem_u32(const void* p) {
    uint32_t a;
    asm("{ .reg .u64 t; cvta.to.shared.u64 t, %1; cvt.u32.u64 %0, t; }"
        : "=r"(a) : "l"(p));
    return a;
}
__device__ __forceinline__ void mma_bf16(float* c, uint32_t a0, uint32_t a1,
                                         uint32_t a2, uint32_t a3,
                                         uint32_t b0, uint32_t b1) {
    asm volatile(
        "mma.sync.aligned.m16n8k16.row.col.f32.bf16.bf16.f32 "
        "{%0,%1,%2,%3},{%4,%5,%6,%7},{%8,%9},{%0,%1,%2,%3};"
        : "+f"(c[0]), "+f"(c[1]), "+f"(c[2]), "+f"(c[3])
        : "r"(a0), "r"(a1), "r"(a2), "r"(a3), "r"(b0), "r"(b1));
}
__device__ __forceinline__ void ldsm_x4(uint32_t& r0, uint32_t& r1, uint32_t& r2,
                                        uint32_t& r3, uint32_t addr) {
    asm volatile("ldmatrix.sync.aligned.m8n8.x4.shared.b16 {%0,%1,%2,%3}, [%4];"
                 : "=r"(r0), "=r"(r1), "=r"(r2), "=r"(r3) : "r"(addr));
}
__device__ __forceinline__ void ldsm_x2(uint32_t& r0, uint32_t& r1, uint32_t addr) {
    asm volatile("ldmatrix.sync.aligned.m8n8.x2.shared.b16 {%0,%1}, [%2];"
                 : "=r"(r0), "=r"(r1) : "r"(addr));
}
__device__ __forceinline__ void ldsm_x2t(uint32_t& r0, uint32_t& r1, uint32_t addr) {
    asm volatile("ldmatrix.sync.aligned.m8n8.x2.trans.shared.b16 {%0,%1}, [%2];"
                 : "=r"(r0), "=r"(r1) : "r"(addr));
}
__device__ __forceinline__ void cpa16(uint32_t dst, const void* src) {
    asm volatile("cp.async.cg.shared.global [%0], [%1], 16;"
                 :: "r"(dst), "l"(src) : "memory");
}
#define CP_COMMIT() asm volatile("cp.async.commit_group;" ::: "memory")
#define CP_WAIT0() asm volatile("cp.async.wait_group 0;" ::: "memory")

// ============================================================================
// Projection via HMMA: relu(X @ W^T + b) -> bf16 hi/lo.
// ============================================================================
#define PJ_WH 0
#define PJ_WL 34816
#define PJ_XH 69632
#define PJ_XL 87040
#define PROJ_SMEM 104448

__global__ __launch_bounds__(512, 1)
void proj_kernel(const float* __restrict__ X, const float* __restrict__ W,
                 const float* __restrict__ bias,
                 __nv_bfloat16* __restrict__ outHi,
                 __nv_bfloat16* __restrict__ outLo) {
    char* sm = dynsm;
    const uint32_t smu = smem_u32(sm);
    const int tid = threadIdx.x, wid = tid >> 5, lane = tid & 31;
    const int wr = wid & 3, wc = wid >> 2;
    const int g = lane >> 2, t = lane & 3;
    const size_t row0 = (size_t)blockIdx.x * 64;

    uint32_t* WH = (uint32_t*)(sm + PJ_WH);
    uint32_t* WL = (uint32_t*)(sm + PJ_WL);
    uint32_t* XH = (uint32_t*)(sm + PJ_XH);
    uint32_t* XL = (uint32_t*)(sm + PJ_XL);

    const float4* Wg = (const float4*)W;
    #pragma unroll
    for (int it = 0; it < 8; it++) {
        int i = it * 512 + tid;
        int r = i >> 5, c4 = i & 31;
        float4 v = Wg[i];
        uint32_t h0 = pack_bf16x2(v.y, v.x);
        uint32_t l0 = pack_bf16x2(v.y - hi_f(h0), v.x - lo_f(h0));
        uint32_t h1 = pack_bf16x2(v.w, v.z);
        uint32_t l1 = pack_bf16x2(v.w - hi_f(h1), v.z - lo_f(h1));
        WH[r * 68 + c4 * 2] = h0; WH[r * 68 + c4 * 2 + 1] = h1;
        WL[r * 68 + c4 * 2] = l0; WL[r * 68 + c4 * 2 + 1] = l1;
    }
    const float4* Xg = (const float4*)(X + row0 * D_);
    #pragma unroll
    for (int it = 0; it < 4; it++) {
        int i = it * 512 + tid;
        int r = i >> 5, c4 = i & 31;
        float4 v = Xg[i];
        uint32_t h0 = pack_bf16x2(v.y, v.x);
        uint32_t l0 = pack_bf16x2(v.y - hi_f(h0), v.x - lo_f(h0));
        uint32_t h1 = pack_bf16x2(v.w, v.z);
        uint32_t l1 = pack_bf16x2(v.w - hi_f(h1), v.z - lo_f(h1));
        XH[r * 68 + c4 * 2] = h0; XH[r * 68 + c4 * 2 + 1] = h1;
        XL[r * 68 + c4 * 2] = l0; XL[r * 68 + c4 * 2 + 1] = l1;
    }
    __syncthreads();

    const int l7 = lane & 7, l8 = (lane >> 3) & 1, l16 = lane >> 4;
    const uint32_t aoffH = smu + PJ_XH + ((16 * wr + l7 + l8 * 8) * 68 + l16 * 4) * 4;
    const uint32_t aoffL = smu + PJ_XL + ((16 * wr + l7 + l8 * 8) * 68 + l16 * 4) * 4;
    const uint32_t boffH = smu + PJ_WH + ((wc * 32 + l7) * 68 + l8 * 4) * 4;
    const uint32_t boffL = smu + PJ_WL + ((wc * 32 + l7) * 68 + l8 * 4) * 4;

    float accA[4][4], accB[4][4];
    #pragma unroll
    for (int j = 0; j < 4; j++)
        #pragma unroll
        for (int q = 0; q < 4; q++) { accA[j][q] = 0.0f; accB[j][q] = 0.0f; }

    #pragma unroll
    for (int kk = 0; kk < 8; kk++) {
        uint32_t ah0, ah1, ah2, ah3, al0, al1, al2, al3;
        ldsm_x4(ah0, ah1, ah2, ah3, aoffH + kk * 32);
        ldsm_x4(al0, al1, al2, al3, aoffL + kk * 32);
        #pragma unroll
        for (int j = 0; j < 4; j++) {
            uint32_t bh0, bh1, bl0, bl1;
            ldsm_x2(bh0, bh1, boffH + j * 2176 + kk * 32);
            ldsm_x2(bl0, bl1, boffL + j * 2176 + kk * 32);
            mma_bf16(accA[j], ah0, ah1, ah2, ah3, bh0, bh1);
            mma_bf16(accB[j], ah0, ah1, ah2, ah3, bl0, bl1);
            mma_bf16(accB[j], al0, al1, al2, al3, bh0, bh1);
        }
    }

    const int rA = 16 * wr + g;
    const float2* b2 = (const float2*)bias;
    uint32_t* oH = (uint32_t*)outHi;
    uint32_t* oL = (uint32_t*)outLo;
    #pragma unroll
    for (int j = 0; j < 4; j++) {
        const int cpair = wc * 16 + j * 4 + t;
        float2 bb = b2[cpair];
        float o0 = fmaxf(accA[j][0] + accB[j][0] + bb.x, 0.0f);
        float o1 = fmaxf(accA[j][1] + accB[j][1] + bb.y, 0.0f);
        uint32_t h = pack_bf16x2(o1, o0);
        uint32_t l = pack_bf16x2(o1 - hi_f(h), o0 - lo_f(h));
        oH[(row0 + rA) * 64 + cpair] = h;
        oL[(row0 + rA) * 64 + cpair] = l;
        float o2 = fmaxf(accA[j][2] + accB[j][2] + bb.x, 0.0f);
        float o3 = fmaxf(accA[j][3] + accB[j][3] + bb.y, 0.0f);
        uint32_t h2 = pack_bf16x2(o3, o2);
        uint32_t l2 = pack_bf16x2(o3 - hi_f(h2), o2 - lo_f(h2));
        oH[(row0 + rA + 8) * 64 + cpair] = h2;
        oL[(row0 + rA + 8) * 64 + cpair] = l2;
    }
}

// ============================================================================
// Fused attention, register-resident P:
// CTA = (b, 64 n-rows), 512 thr, warp grid 4(n: wr) x 4(m-slice: wc).
// Per chunk (64 m): warp computes scores for rows 16wr..+16 over its own
// m-slice (wc*16..+16, k=128), exps in registers, repacks C-frags as the
// A-fragment of the ctx MMA (k=16), and accumulates a d=128 ctx partial.
// Partials over wc summed once in the epilogue. ONE barrier per chunk.
// ============================================================================
#define OFF_UCH 0
#define OFF_UCL 17408
#define OFF_VH0 34816
#define OFF_VL0 52224
#define OFF_VH1 69632
#define OFF_VL1 87040
#define OFF_RS  104448
#define OFF_INV 105472
#define OFF_RED 105728
#define ATTN_SMEM 107776

__global__ __launch_bounds__(512, 1)
void attn_kernel(float* __restrict__ part) {
    char* sm = dynsm;
    const uint32_t smu = smem_u32(sm);
    const int tid = threadIdx.x, wid = tid >> 5, lane = tid & 31;
    const int wr = wid & 3, wc = wid >> 2;          // 4 x 4 warp grid
    const int g = lane >> 2, t = lane & 3;
    const int b = blockIdx.x >> 3, nt = blockIdx.x & 7;

    uint32_t* UC32h = (uint32_t*)(sm + OFF_UCH);   // stride 68 u32 per row
    uint32_t* UC32l = (uint32_t*)(sm + OFF_UCL);
    float* RS  = (float*)(sm + OFF_RS);
    float* INV = (float*)(sm + OFF_INV);
    float* RED = (float*)(sm + OFF_RED);

    const uint4* ucHg = (const uint4*)(g_UcHi + ((size_t)(b * N_ + nt * 64)) * D_);
    const uint4* ucLg = (const uint4*)(g_UcLo + ((size_t)(b * N_ + nt * 64)) * D_);
    const uint4* vpHg = (const uint4*)(g_VpHi + (size_t)b * M_ * D_);
    const uint4* vpLg = (const uint4*)(g_VpLo + (size_t)b * M_ * D_);

    // stage Uc (64 rows x 16 uint4 per buffer)
    uint4* UH4 = (uint4*)(sm + OFF_UCH);
    uint4* UL4 = (uint4*)(sm + OFF_UCL);
    #pragma unroll
    for (int it = 0; it < 2; it++) {
        int i = it * 512 + tid;
        int r = i >> 4, c = i & 15;
        UH4[r * 17 + c] = ucHg[i];
        UL4[r * 17 + c] = ucLg[i];
    }

    const uint32_t vhB[2] = {smu + OFF_VH0, smu + OFF_VH1};
    const uint32_t vlB[2] = {smu + OFF_VL0, smu + OFF_VL1};

    const int l7 = lane & 7, l8 = (lane >> 3) & 1, l16 = lane >> 4;
    // A (scores/Uc): rows 16wr..+16, x4
    const uint32_t aoffH = smu + OFF_UCH + ((16 * wr + l7 + l8 * 8) * 68 + l16 * 4) * 4;
    const uint32_t aoffL = smu + OFF_UCL + ((16 * wr + l7 + l8 * 8) * 68 + l16 * 4) * 4;
    // B (scores/V): m-rows wc*16 + j*8, x2 non-trans
    const uint32_t boffV = ((wc * 16 + l7) * 68 + l8 * 4) * 4;
    // B (ctx): trans: k-rows = m-slice wc*16 + l8*8 + l7 fixed; d via +j*16B
    const uint32_t boffT = ((wc * 16 + l8 * 8 + l7) * 68) * 4;

    const int rA = 16 * wr + g;
    float cacc[16][4];
    #pragma unroll
    for (int j = 0; j < 16; j++)
        #pragma unroll
        for (int q = 0; q < 4; q++) cacc[j][q] = 0.0f;
    float rs0 = 0.0f, rs1 = 0.0f;

    // stage chunk 0
    #pragma unroll
    for (int it = 0; it < 2; it++) {
        int i = it * 512 + tid;
        int r = i >> 4, c = i & 15;
        cpa16(vhB[0] + (r * 68 + c * 4) * 4, vpHg + r * 16 + c);
        cpa16(vlB[0] + (r * 68 + c * 4) * 4, vpLg + r * 16 + c);
    }
    CP_COMMIT();

    for (int mc = 0; mc < 16; mc++) {
        const int s = mc & 1;
        CP_WAIT0();
        __syncthreads();
        if (mc + 1 < 16) {
            const int s2 = s ^ 1;
            #pragma unroll
            for (int it = 0; it < 2; it++) {
                int i = it * 512 + tid;
                int r = i >> 4, c = i & 15;
                cpa16(vhB[s2] + (r * 68 + c * 4) * 4,
                      vpHg + ((mc + 1) * 64 + r) * 16 + c);
                cpa16(vlB[s2] + (r * 68 + c * 4) * 4,
                      vpLg + ((mc + 1) * 64 + r) * 16 + c);
            }
            CP_COMMIT();
        }

        // ---- scores: 16n x 16m (own m-slice), k=128 ----
        float accA[2][4], accB[2][4];
        #pragma unroll
        for (int j = 0; j < 2; j++)
            #pragma unroll
            for (int q = 0; q < 4; q++) { accA[j][q] = 0.0f; accB[j][q] = 0.0f; }

        const uint32_t bvh = vhB[s] + boffV, bvl = vlB[s] + boffV;
        #pragma unroll
        for (int kk = 0; kk < 8; kk++) {
            uint32_t ah0, ah1, ah2, ah3, al0, al1, al2, al3;
            ldsm_x4(ah0, ah1, ah2, ah3, aoffH + kk * 32);
            ldsm_x4(al0, al1, al2, al3, aoffL + kk * 32);
            #pragma unroll
            for (int j = 0; j < 2; j++) {
                uint32_t bh0, bh1, bl0, bl1;
                ldsm_x2(bh0, bh1, bvh + j * 2176 + kk * 32);
                ldsm_x2(bl0, bl1, bvl + j * 2176 + kk * 32);
                mma_bf16(accA[j], ah0, ah1, ah2, ah3, bh0, bh1);
                mma_bf16(accB[j], ah0, ah1, ah2, ah3, bl0, bl1);
                mma_bf16(accB[j], al0, al1, al2, al3, bh0, bh1);
            }
        }

        // ---- exp in registers; C-frags -> ctx A-frags (no smem) ----
        float e0 = __expf(accA[0][0] + accB[0][0] - 40.0f);
        float e1 = __expf(accA[0][1] + accB[0][1] - 40.0f);
        float e2 = __expf(accA[0][2] + accB[0][2] - 40.0f);
        float e3 = __expf(accA[0][3] + accB[0][3] - 40.0f);
        float f0 = __expf(accA[1][0] + accB[1][0] - 40.0f);
        float f1 = __expf(accA[1][1] + accB[1][1] - 40.0f);
        float f2 = __expf(accA[1][2] + accB[1][2] - 40.0f);
        float f3 = __expf(accA[1][3] + accB[1][3] - 40.0f);
        rs0 += e0 + e1 + f0 + f1;
        rs1 += e2 + e3 + f2 + f3;
        // A-frag: a0=(row g, k 2t..2t+1), a1=(g+8, same), a2=(g, 2t+8..), a3=(g+8,..)
        uint32_t ph0 = pack_bf16x2(e1, e0);
        uint32_t ph1 = pack_bf16x2(e3, e2);
        uint32_t ph2 = pack_bf16x2(f1, f0);
        uint32_t ph3 = pack_bf16x2(f3, f2);
        uint32_t pl0 = pack_bf16x2(e1 - hi_f(ph0), e0 - lo_f(ph0));
        uint32_t pl1 = pack_bf16x2(e3 - hi_f(ph1), e2 - lo_f(ph1));
        uint32_t pl2 = pack_bf16x2(f1 - hi_f(ph2), f0 - lo_f(ph2));
        uint32_t pl3 = pack_bf16x2(f3 - hi_f(ph3), f2 - lo_f(ph3));

        // ---- ctx partial: 16n x 128d, k=16 (own m-slice) ----
        const uint32_t bth = vhB[s] + boffT, btl = vlB[s] + boffT;
        #pragma unroll
        for (int j = 0; j < 16; j++) {
            uint32_t bh0, bh1, bl0, bl1;
            ldsm_x2t(bh0, bh1, bth + j * 16);
            ldsm_x2t(bl0, bl1, btl + j * 16);
            mma_bf16(cacc[j], ph0, ph1, ph2, ph3, bh0, bh1);
            mma_bf16(cacc[j], pl0, pl1, pl2, pl3, bh0, bh1);
            mma_bf16(cacc[j], ph0, ph1, ph2, ph3, bl0, bl1);
        }
    }

    // ---- row sums -> inverse (4 wc m-slices per row) ----
    rs0 += __shfl_xor_sync(0xffffffffu, rs0, 1);
    rs0 += __shfl_xor_sync(0xffffffffu, rs0, 2);
    rs1 += __shfl_xor_sync(0xffffffffu, rs1, 1);
    rs1 += __shfl_xor_sync(0xffffffffu, rs1, 2);
    if (t == 0) {
        RS[wc * 64 + rA] = rs0;
        RS[wc * 64 + rA + 8] = rs1;
    }
    __syncthreads();
    if (tid < 64)
        INV[tid] = 1.0f / (RS[tid] + RS[64 + tid] + RS[128 + tid] + RS[192 + tid]);
    __syncthreads();

    // ---- sum ctx partials over wc into Jt (raw, unnormalized) ----
    float* Jt = (float*)(sm + OFF_VH0);   // 64 x 132 f32 (reuses V area)
    #pragma unroll
    for (int p = 0; p < 4; p++) {
        if (wc == p) {
            #pragma unroll
            for (int j = 0; j < 16; j++) {
                const int d0 = j * 8 + 2 * t;
                if (p == 0) {
                    Jt[rA * 132 + d0]           = cacc[j][0];
                    Jt[rA * 132 + d0 + 1]       = cacc[j][1];
                    Jt[(rA + 8) * 132 + d0]     = cacc[j][2];
                    Jt[(rA + 8) * 132 + d0 + 1] = cacc[j][3];
                } else {
                    Jt[rA * 132 + d0]           += cacc[j][0];
                    Jt[rA * 132 + d0 + 1]       += cacc[j][1];
                    Jt[(rA + 8) * 132 + d0]     += cacc[j][2];
                    Jt[(rA + 8) * 132 + d0 + 1] += cacc[j][3];
                }
            }
        }
        __syncthreads();
    }

    // ---- n-reduce: sum over rows of (Uc + ctx*inv) ----
    {
        int h = tid >> 7, d = tid & 127;   // 4 groups x 16 rows
        float s = 0.0f;
        #pragma unroll
        for (int r = 0; r < 16; r++) {
            int row = h * 16 + r;
            uint32_t uh = UC32h[row * 68 + (d >> 1)];
            uint32_t ul = UC32l[row * 68 + (d >> 1)];
            float uc = (d & 1) ? (hi_f(uh) + hi_f(ul)) : (lo_f(uh) + lo_f(ul));
            s += uc + Jt[row * 132 + d] * INV[row];
        }
        RED[h * 128 + d] = s;
    }
    __syncthreads();
    if (tid < 128)
        part[(size_t)blockIdx.x * D_ + tid] =
            RED[tid] + RED[128 + tid] + RED[256 + tid] + RED[384 + tid];
}

// ============================================================================
__global__ __launch_bounds__(256)
void reduce_kernel(const float* __restrict__ part, const float* __restrict__ q,
                   float* __restrict__ out) {
    int i = blockIdx.x * blockDim.x + threadIdx.x;
    int b = i >> 7, d = i & 127;
    float s = 0.0f;
    #pragma unroll
    for (int nt = 0; nt < 8; nt++)
        s += part[(size_t)(b * 8 + nt) * D_ + d];
    out[i] = s * q[d] * (1.0f / (float)N_);
}

// ============================================================================
extern "C" void kernel_launch(void* const* d_in, const int* in_sizes, int n_in,
                              void* d_out, int out_size) {
    const float* h_c = (const float*)d_in[0];
    const float* h_p = (const float*)d_in[1];
    const float* U_w = (const float*)d_in[2];
    const float* U_b = (const float*)d_in[3];
    const float* V_w = (const float*)d_in[4];
    const float* V_b = (const float*)d_in[5];
    const float* q   = (const float*)d_in[6];
    float* out = (float*)d_out;

    void *pUcH, *pUcL, *pVpH, *pVpL, *pPart;
    cudaGetSymbolAddress(&pUcH, g_UcHi);
    cudaGetSymbolAddress(&pUcL, g_UcLo);
    cudaGetSymbolAddress(&pVpH, g_VpHi);
    cudaGetSymbolAddress(&pVpL, g_VpLo);
    cudaGetSymbolAddress(&pPart, g_part);

    cudaFuncSetAttribute(proj_kernel,
                         cudaFuncAttributeMaxDynamicSharedMemorySize, PROJ_SMEM);
    cudaFuncSetAttribute(attn_kernel,
                         cudaFuncAttributeMaxDynamicSharedMemorySize, ATTN_SMEM);

    proj_kernel<<<(B_ * N_) / 64, 512, PROJ_SMEM>>>(
        h_c, U_w, U_b, (__nv_bfloat16*)pUcH, (__nv_bfloat16*)pUcL);
    proj_kernel<<<(B_ * M_) / 64, 512, PROJ_SMEM>>>(
        h_p, V_w, V_b, (__nv_bfloat16*)pVpH, (__nv_bfloat16*)pVpL);
    attn_kernel<<<B_ * 8, 512, ATTN_SMEM>>>((float*)pPart);
    reduce_kernel<<<(B_ * D_) / 256, 256>>>((const float*)pPart, q, out);
}